// round 5
// baseline (speedup 1.0000x reference)
#include <cuda_runtime.h>
#include <math.h>

// ---------------------------------------------------------------------------
// MultilayerGRU: B=32, S=512, I=H=O=1024, L=2
// R5: (A) sgemm re-tiled 128x128 / 8x8 micro-tile (FFMA-bound, was LDS-bound)
//     (B) recurrence: pipelined chunked tile loads, split arrive/wait grid
//         barrier with pre-wait loads, k_prep resets barrier state per launch.
// ---------------------------------------------------------------------------

#define B_  32
#define S_  512
#define IN_ 1024
#define H_  1024
#define OUT_ 1024
#define L_  2
#define M_  (B_ * S_)      /* 16384 */
#define N3_ (3 * H_)       /* 3072  */

#define PITCH 1024                          /* words; [b][k] tile */
#define TILE_WORDS (B_ * PITCH)             /* 32768 */
#define WG_WORDS   (8 * H_)                 /* 8192: 8 phase-2 weight cols */
#define SMEM_BYTES ((TILE_WORDS + WG_WORDS) * 4)  /* 163840 */
#define NBLK 128            /* persistent grid; <=148 SMs, 1 blk/SM */

// ---------------- device scratch (static allocation is allowed) ------------
__device__ float g_xT[(size_t)M_ * IN_];   // x re-laid out to [t*B+b, i]
__device__ float g_gx[(size_t)M_ * N3_];   // x-projections for current layer
__device__ float g_seq[(size_t)M_ * H_];   // layer hidden sequence [t*B+b, h]
__device__ float g_h[B_ * H_];             // current hidden state
__device__ float g_z[B_ * H_];             // z gate for current step
__device__ float g_rh[B_ * H_];            // r * h for current step

// grid barrier state (reset by k_prep before each recurrence launch)
__device__ unsigned g_bar_count;
__device__ unsigned g_bar_gen;

__device__ __forceinline__ void bar_arrive(unsigned gen_val) {
    __syncthreads();                       // block's writes done
    if (threadIdx.x == 0) {
        __threadfence();                   // publish writes
        if (atomicAdd(&g_bar_count, 1u) == NBLK - 1u) {
            g_bar_count = 0;               // reset BEFORE gen publish
            __threadfence();
            *(volatile unsigned*)&g_bar_gen = gen_val;
        }
    }
}

__device__ __forceinline__ void bar_wait(unsigned gen_val) {
    if (threadIdx.x == 0) {
        while (*(volatile unsigned*)&g_bar_gen < gen_val) { }
        __threadfence();                   // acquire
    }
    __syncthreads();
}

// ---------------------------------------------------------------------------
// x[b][t][i] -> g_xT[(t*B+b)][i]
// ---------------------------------------------------------------------------
__global__ void k_transpose_x(const float* __restrict__ x) {
    int row = blockIdx.x;               // t*B + b
    int t = row / B_;
    int b = row % B_;
    const float4* src = (const float4*)(x + ((size_t)b * S_ + t) * IN_);
    float4* dst = (float4*)(g_xT + (size_t)row * IN_);
    for (int i = threadIdx.x; i < IN_ / 4; i += blockDim.x) dst[i] = src[i];
}

// ---------------------------------------------------------------------------
// k_prep: g_h[b][c] = h0[b][layer][c]; also reset grid-barrier state.
// ---------------------------------------------------------------------------
__global__ void k_prep(const float* __restrict__ h0, int layer) {
    int idx = blockIdx.x * blockDim.x + threadIdx.x;  // [0, B*H)
    if (idx == 0) { g_bar_count = 0; g_bar_gen = 0; }
    int b = idx / H_;
    int c = idx % H_;
    g_h[idx] = h0[((size_t)b * L_ + layer) * H_ + c];
}

// ---------------------------------------------------------------------------
// Tiled SGEMM:  C[m][n] = sum_k A[m][k] * W[n][k]  + bias[n]
//   BM=BN=128, BK=16, 256 threads, 8x8 micro-tile, register prefetch.
//   permC=0: C = g_gx, index (m*ldc + col0 + n)
//   permC=1: C = Cout, index ((b*S + t)*ldc + n) with m = t*B + b
// ---------------------------------------------------------------------------
#define SG_BK 16
__global__ void __launch_bounds__(256) k_sgemm(
    int asel,
    const float* __restrict__ W,
    const float* __restrict__ bias,
    float* __restrict__ Cout,
    int K, int ldc, int col0, int permC)
{
    const float* __restrict__ A = asel ? g_seq : g_xT;

    __shared__ float As[SG_BK][132];
    __shared__ float Ws[SG_BK][132];

    const int m0 = blockIdx.y * 128;
    const int n0 = blockIdx.x * 128;
    const int tid = threadIdx.x;

    // loader mapping: 256 thr -> 128 rows x 2 k-halves (8 floats each)
    const int lrow = tid >> 1;
    const int lk   = (tid & 1) * 8;
    const float* Ap = A + (size_t)(m0 + lrow) * K + lk;
    const float* Wp = W + (size_t)(n0 + lrow) * K + lk;

    // compute mapping: 8 warps as 2(m) x 4(n); lane 8(m) x 4(n); 8x8 thread tile
    const int warp = tid >> 5, lane = tid & 31;
    const int mB = (warp & 1) * 64 + (lane & 7) * 8;
    const int nB = (warp >> 1) * 32 + (lane >> 3) * 8;

    float acc[8][8];
#pragma unroll
    for (int i = 0; i < 8; i++)
#pragma unroll
        for (int j = 0; j < 8; j++) acc[i][j] = 0.f;

    float4 a0 = *(const float4*)Ap, a1 = *(const float4*)(Ap + 4);
    float4 b0 = *(const float4*)Wp, b1 = *(const float4*)(Wp + 4);

    for (int k0 = 0; k0 < K; k0 += SG_BK) {
        __syncthreads();   // previous compute done before overwrite
        As[lk + 0][lrow] = a0.x; As[lk + 1][lrow] = a0.y;
        As[lk + 2][lrow] = a0.z; As[lk + 3][lrow] = a0.w;
        As[lk + 4][lrow] = a1.x; As[lk + 5][lrow] = a1.y;
        As[lk + 6][lrow] = a1.z; As[lk + 7][lrow] = a1.w;
        Ws[lk + 0][lrow] = b0.x; Ws[lk + 1][lrow] = b0.y;
        Ws[lk + 2][lrow] = b0.z; Ws[lk + 3][lrow] = b0.w;
        Ws[lk + 4][lrow] = b1.x; Ws[lk + 5][lrow] = b1.y;
        Ws[lk + 6][lrow] = b1.z; Ws[lk + 7][lrow] = b1.w;
        if (k0 + SG_BK < K) {
            Ap += SG_BK; Wp += SG_BK;
            a0 = *(const float4*)Ap; a1 = *(const float4*)(Ap + 4);
            b0 = *(const float4*)Wp; b1 = *(const float4*)(Wp + 4);
        }
        __syncthreads();

#pragma unroll
        for (int k = 0; k < SG_BK; k++) {
            float av[8], wv[8];
            *(float4*)(av)     = *(const float4*)&As[k][mB];
            *(float4*)(av + 4) = *(const float4*)&As[k][mB + 4];
            *(float4*)(wv)     = *(const float4*)&Ws[k][nB];
            *(float4*)(wv + 4) = *(const float4*)&Ws[k][nB + 4];
#pragma unroll
            for (int i = 0; i < 8; i++)
#pragma unroll
                for (int j = 0; j < 8; j++)
                    acc[i][j] = fmaf(av[i], wv[j], acc[i][j]);
        }
    }

    // epilogue
    float bv[8];
    if (bias) {
        *(float4*)(bv)     = *(const float4*)(bias + n0 + nB);
        *(float4*)(bv + 4) = *(const float4*)(bias + n0 + nB + 4);
    } else {
#pragma unroll
        for (int j = 0; j < 8; j++) bv[j] = 0.f;
    }
#pragma unroll
    for (int i = 0; i < 8; i++) {
        int m = m0 + mB + i;
        float o[8];
#pragma unroll
        for (int j = 0; j < 8; j++) o[j] = acc[i][j] + bv[j];
        float* dst;
        if (permC) {
            int b = m & (B_ - 1);
            int t = m >> 5;
            dst = Cout + ((size_t)b * S_ + t) * ldc + n0 + nB;
        } else {
            dst = g_gx + (size_t)m * ldc + col0 + n0 + nB;
        }
        *(float4*)(dst)     = *(const float4*)(o);
        *(float4*)(dst + 4) = *(const float4*)(o + 4);
    }
}

// ---------------------------------------------------------------------------
// Chunked tile load helpers: tile = 32 rows (b) x 256 float4 (k), 4 chunks of
// 64 float4-columns. Per chunk per warp: 8 LDG.128 + 8 STS.128, coalesced and
// bank-conflict-free.
// ---------------------------------------------------------------------------
__device__ __forceinline__ void chunk_ldg(const float* __restrict__ src,
                                          int c, int warp, int lane, float4* v) {
    const int kq = c * 64 + warp * 8 + (lane & 7);
    const int b0 = lane >> 3;
#pragma unroll
    for (int iu = 0; iu < 8; iu++) {
        int b = iu * 4 + b0;
        v[iu] = __ldcg(reinterpret_cast<const float4*>(src + (size_t)b * H_) + kq);
    }
}

__device__ __forceinline__ void chunk_sts(float* __restrict__ s_h,
                                          int c, int warp, int lane, const float4* v) {
    const int kq = c * 64 + warp * 8 + (lane & 7);
    const int b0 = lane >> 3;
#pragma unroll
    for (int iu = 0; iu < 8; iu++) {
        int b = iu * 4 + b0;
        reinterpret_cast<float4*>(s_h + (size_t)b * PITCH)[kq] = v[iu];
    }
}

// ---------------------------------------------------------------------------
// Multi-reduce: 32 per-lane partial arrays -> lane l returns total of array l.
// ---------------------------------------------------------------------------
__device__ __forceinline__ float warp_multireduce(float* a, int lane) {
#pragma unroll
    for (int off = 16; off >= 1; off >>= 1) {
#pragma unroll
        for (int b = 0; b < off; b++) {
            bool hi = (lane & off) != 0;
            float send = hi ? a[b] : a[b + off];
            float recv = __shfl_xor_sync(0xffffffffu, send, off);
            a[b] = (hi ? a[b + off] : a[b]) + recv;
        }
    }
    return a[0];
}

__device__ __forceinline__ float sigmoidf_(float x) {
    return 1.f / (1.f + expf(-x));
}

// ---------------------------------------------------------------------------
// Persistent recurrence kernel. NBLK(128) x 256 thr, 160KB dyn smem ->
// 1 block/SM, all resident; split arrive/wait grid barrier.
//
// Phase 1: 8 warps x 2 cols of (z|r); weights in registers.
// Phase 2: warps 0-3 x 2 cols of g; weights in smem; warps 4-7 help load.
// Tile loads pipelined in 4 chunks (LDG c+1 issued before compute of c).
// ---------------------------------------------------------------------------
__global__ void __launch_bounds__(256, 1) k_gru_recur(
    const float* __restrict__ Wzh, const float* __restrict__ Wrh,
    const float* __restrict__ Wgh, int layer, float* __restrict__ hid_out)
{
    extern __shared__ float smem[];
    float* s_h  = smem;                    // [32][1024]
    float* s_wg = smem + TILE_WORDS;       // [8][1024]

    const int warp = threadIdx.x >> 5;
    const int lane = threadIdx.x & 31;

    // ---- phase-1 static assignment: 2 cols per warp over z(1024)+r(1024)
    const int vc   = blockIdx.x * 16 + warp * 2;
    const int gate = vc >> 10;             // 0=z, 1=r
    const int c1   = vc & 1023;
    const float* Wb = gate ? Wrh : Wzh;
    const float* W0 = Wb + ((size_t)layer * H_ + c1) * H_;
    const float* W1 = W0 + H_;
    const int goff = gate ? H_ : 0;

    float4 w0r[8], w1r[8];                 // weight stripes, live whole kernel
#pragma unroll
    for (int kc = 0; kc < 8; kc++) {
        w0r[kc] = reinterpret_cast<const float4*>(W0 + kc * 128)[lane];
        w1r[kc] = reinterpret_cast<const float4*>(W1 + kc * 128)[lane];
    }

    // ---- phase-2 static assignment: warps 0..3, 2 cols each
    const int c2 = blockIdx.x * 8 + (warp & 3) * 2;

    // phase-2 weights -> smem once (8 cols x 1024)
    for (int cc = 0; cc < 8; cc++) {
        const float4* src = reinterpret_cast<const float4*>(
            Wgh + ((size_t)layer * H_ + blockIdx.x * 8 + cc) * H_);
        reinterpret_cast<float4*>(s_wg + cc * H_)[threadIdx.x] = src[threadIdx.x];
    }
    __syncthreads();

    unsigned tgt = 0;
    // preload phase-1 gx for t=0
    float gx0 = __ldcg(&g_gx[(size_t)lane * N3_ + goff + c1]);
    float gx1 = __ldcg(&g_gx[(size_t)lane * N3_ + goff + c1 + 1]);

    for (int t = 0; t < S_; t++) {
        const size_t row = (size_t)t * B_ + lane;     // b = lane

        // ================= phase 1: z and r =================
        float accA[32], accB[32];
#pragma unroll
        for (int b = 0; b < 32; b++) { accA[b] = 0.f; accB[b] = 0.f; }

        {
            float4 v[8];
            chunk_ldg(g_h, 0, warp, lane, v);
#pragma unroll
            for (int c = 0; c < 4; c++) {
                chunk_sts(s_h, c, warp, lane, v);
                if (c < 3) chunk_ldg(g_h, c + 1, warp, lane, v);
                __syncthreads();
#pragma unroll
                for (int kk = 0; kk < 2; kk++) {
                    const int kc = c * 2 + kk;
                    const float4* hp = reinterpret_cast<const float4*>(s_h + kc * 128) + lane;
                    const float4 w0 = w0r[kc], w1 = w1r[kc];
#pragma unroll
                    for (int b = 0; b < 32; b++) {
                        float4 h4 = hp[b * 256];
                        accA[b] = fmaf(h4.x, w0.x, accA[b]);
                        accA[b] = fmaf(h4.y, w0.y, accA[b]);
                        accA[b] = fmaf(h4.z, w0.z, accA[b]);
                        accA[b] = fmaf(h4.w, w0.w, accA[b]);
                        accB[b] = fmaf(h4.x, w1.x, accB[b]);
                        accB[b] = fmaf(h4.y, w1.y, accB[b]);
                        accB[b] = fmaf(h4.z, w1.z, accB[b]);
                        accB[b] = fmaf(h4.w, w1.w, accB[b]);
                    }
                }
            }
        }
        float v0 = warp_multireduce(accA, lane);
        float v1 = warp_multireduce(accB, lane);

        if (gate == 0) {
            g_z[lane * H_ + c1]     = sigmoidf_(v0 + gx0);
            g_z[lane * H_ + c1 + 1] = sigmoidf_(v1 + gx1);
        } else {
            float h0v = s_h[lane * PITCH + c1];        // own h from tile
            float h1v = s_h[lane * PITCH + c1 + 1];
            g_rh[lane * H_ + c1]     = sigmoidf_(v0 + gx0) * h0v;
            g_rh[lane * H_ + c1 + 1] = sigmoidf_(v1 + gx1) * h1v;
        }

        bar_arrive(++tgt);

        // pre-wait loads (safe: own columns / constant data)
        float gxg0 = 0.f, gxg1 = 0.f, hv0 = 0.f, hv1 = 0.f;
        if (warp < 4) {
            gxg0 = __ldcg(&g_gx[row * N3_ + 2 * H_ + c2]);
            gxg1 = __ldcg(&g_gx[row * N3_ + 2 * H_ + c2 + 1]);
            hv0  = g_h[lane * H_ + c2];     // only self writes these cols
            hv1  = g_h[lane * H_ + c2 + 1];
        }

        bar_wait(tgt);

        // ================= phase 2: g and h update =================
        float zv0 = 0.f, zv1 = 0.f;
        if (warp < 4) {
            zv0 = __ldcg(&g_z[lane * H_ + c2]);        // needs barrier
            zv1 = __ldcg(&g_z[lane * H_ + c2 + 1]);
        }

        float acc0[32], acc1[32];
#pragma unroll
        for (int b = 0; b < 32; b++) { acc0[b] = 0.f; acc1[b] = 0.f; }

        {
            float4 v[8];
            chunk_ldg(g_rh, 0, warp, lane, v);
#pragma unroll
            for (int c = 0; c < 4; c++) {
                chunk_sts(s_h, c, warp, lane, v);
                if (c < 3) chunk_ldg(g_rh, c + 1, warp, lane, v);
                __syncthreads();
                if (warp < 4) {
#pragma unroll
                    for (int kk = 0; kk < 2; kk++) {
                        const int kc = c * 2 + kk;
                        const float4* hp = reinterpret_cast<const float4*>(s_h + kc * 128) + lane;
                        float4 wA = reinterpret_cast<const float4*>(
                            s_wg + ((warp & 3) * 2) * H_ + kc * 128)[lane];
                        float4 wB = reinterpret_cast<const float4*>(
                            s_wg + ((warp & 3) * 2 + 1) * H_ + kc * 128)[lane];
#pragma unroll
                        for (int b = 0; b < 32; b++) {
                            float4 h4 = hp[b * 256];
                            acc0[b] = fmaf(h4.x, wA.x, acc0[b]);
                            acc0[b] = fmaf(h4.y, wA.y, acc0[b]);
                            acc0[b] = fmaf(h4.z, wA.z, acc0[b]);
                            acc0[b] = fmaf(h4.w, wA.w, acc0[b]);
                            acc1[b] = fmaf(h4.x, wB.x, acc1[b]);
                            acc1[b] = fmaf(h4.y, wB.y, acc1[b]);
                            acc1[b] = fmaf(h4.z, wB.z, acc1[b]);
                            acc1[b] = fmaf(h4.w, wB.w, acc1[b]);
                        }
                    }
                }
            }
        }

        if (warp < 4) {
            float vg0 = warp_multireduce(acc0, lane);
            float vg1 = warp_multireduce(acc1, lane);

            float gv0 = tanhf(vg0 + gxg0);
            float gv1 = tanhf(vg1 + gxg1);
            float hn0 = fmaf(zv0, gv0 - hv0, hv0);
            float hn1 = fmaf(zv1, gv1 - hv1, hv1);

            g_h[lane * H_ + c2]     = hn0;
            g_h[lane * H_ + c2 + 1] = hn1;
            g_seq[row * H_ + c2]     = hn0;
            g_seq[row * H_ + c2 + 1] = hn1;
            if (hid_out && t == S_ - 1) {
                hid_out[((size_t)lane * L_ + layer) * H_ + c2]     = hn0;
                hid_out[((size_t)lane * L_ + layer) * H_ + c2 + 1] = hn1;
            }
        }

        bar_arrive(++tgt);

        // pre-wait loads for next step's phase 1 (constant data)
        if (t + 1 < S_) {
            gx0 = __ldcg(&g_gx[((size_t)(t + 1) * B_ + lane) * N3_ + goff + c1]);
            gx1 = __ldcg(&g_gx[((size_t)(t + 1) * B_ + lane) * N3_ + goff + c1 + 1]);
            bar_wait(tgt);   // h(t+1) ready
        }
    }
}

// ---------------------------------------------------------------------------
// Launch
// ---------------------------------------------------------------------------
extern "C" void kernel_launch(void* const* d_in, const int* in_sizes, int n_in,
                              void* d_out, int out_size) {
    (void)in_sizes; (void)n_in;
    const float* x   = (const float*)d_in[0];
    const float* h0  = (const float*)d_in[1];
    const float* Wzx = (const float*)d_in[2];
    const float* bz  = (const float*)d_in[3];
    const float* Wzh = (const float*)d_in[4];
    const float* Wrx = (const float*)d_in[5];
    const float* br  = (const float*)d_in[6];
    const float* Wrh = (const float*)d_in[7];
    const float* Wgx = (const float*)d_in[8];
    const float* bg  = (const float*)d_in[9];
    const float* Wgh = (const float*)d_in[10];
    const float* Wo  = (const float*)d_in[11];
    const float* bo  = (const float*)d_in[12];

    float* out = (float*)d_out;
    float* y_out = out;                                  // [B,S,O]
    const long long need = (long long)B_ * S_ * OUT_ + (long long)B_ * L_ * H_;
    float* hid_out = ((long long)out_size >= need) ? out + (size_t)B_ * S_ * OUT_
                                                   : nullptr;

    cudaFuncSetAttribute(k_gru_recur,
        cudaFuncAttributeMaxDynamicSharedMemorySize, SMEM_BYTES);

    // 1) x -> [t*B+b, i]
    k_transpose_x<<<M_, 256>>>(x);

    dim3 ggrid(OUT_ / 128, M_ / 128);  // (8, 128)

    for (int layer = 0; layer < L_; layer++) {
        k_prep<<<(B_ * H_) / 256, 256>>>(h0, layer);

        int asel = (layer == 0) ? 0 : 1;
        const size_t wxo = (size_t)layer * H_ * IN_;
        k_sgemm<<<ggrid, 256>>>(asel, Wzx + wxo, bz + (size_t)layer * H_,
                                nullptr, IN_, N3_, 0, 0);
        k_sgemm<<<ggrid, 256>>>(asel, Wrx + wxo, br + (size_t)layer * H_,
                                nullptr, IN_, N3_, H_, 0);
        k_sgemm<<<ggrid, 256>>>(asel, Wgx + wxo, bg + (size_t)layer * H_,
                                nullptr, IN_, N3_, 2 * H_, 0);

        // full-sequence recurrence in ONE persistent launch
        k_gru_recur<<<NBLK, 256, SMEM_BYTES>>>(Wzh, Wrh, Wgh, layer, hid_out);
    }

    // output projection: y[b][t][:] = seq[t*B+b][:] @ Wo^T + bo
    k_sgemm<<<ggrid, 256>>>(1, Wo, bo, y_out, H_, OUT_, 0, 1);
}

// round 7
// speedup vs baseline: 1.1552x; 1.1552x over previous
#include <cuda_runtime.h>
#include <cuda_bf16.h>
#include <math.h>
#include <stdint.h>

// ---------------------------------------------------------------------------
// MultilayerGRU: B=32, S=512, I=H=O=1024, L=2
// R7: big GEMMs on warp-level mma.sync (HMMA, bf16 hi/lo 3-term split ->
//     fp32-grade accuracy). tcgen05 is unavailable: harness ptxas targets
//     sm_103 (no 'a' feature set). Recurrence = proven R4 loop + bf16 seq
//     stores.
// ---------------------------------------------------------------------------

#define B_  32
#define S_  512
#define IN_ 1024
#define H_  1024
#define OUT_ 1024
#define L_  2
#define M_  (B_ * S_)      /* 16384 */
#define N3_ (3 * H_)       /* 3072  */

#define PITCH 1024                          /* words; [b][k] tile */
#define TILE_WORDS (B_ * PITCH)             /* 32768 */
#define WG_WORDS   (8 * H_)                 /* 8192 */
#define SMEM_BYTES ((TILE_WORDS + WG_WORDS) * 4)  /* 163840 */
#define NBLK 128

// ---------------- device scratch ------------------------------------------
__device__ float g_gx[(size_t)M_ * N3_];   // x-projections for current layer
__device__ float g_h[B_ * H_];             // current hidden state
__device__ float g_z[B_ * H_];             // z gate
__device__ float g_rh[B_ * H_];            // r * h

// bf16 hi/lo operand buffers (raw ushort)
__device__ unsigned short g_xh[(size_t)M_ * IN_],  g_xl[(size_t)M_ * IN_];
__device__ unsigned short g_seqh[(size_t)M_ * H_], g_seql[(size_t)M_ * H_];
__device__ unsigned short g_wzxh[(size_t)L_ * H_ * IN_], g_wzxl[(size_t)L_ * H_ * IN_];
__device__ unsigned short g_wrxh[(size_t)L_ * H_ * IN_], g_wrxl[(size_t)L_ * H_ * IN_];
__device__ unsigned short g_wgxh[(size_t)L_ * H_ * IN_], g_wgxl[(size_t)L_ * H_ * IN_];
__device__ unsigned short g_woh[(size_t)OUT_ * H_],      g_wol[(size_t)OUT_ * H_];

// grid barrier (generation-based; replay-safe: gen read dynamically)
__device__ unsigned g_bar_count = 0;
__device__ volatile unsigned g_bar_gen = 0;

__device__ __forceinline__ void grid_sync() {
    __syncthreads();
    if (threadIdx.x == 0) {
        __threadfence();
        unsigned gen = g_bar_gen;
        if (atomicAdd(&g_bar_count, 1u) == NBLK - 1u) {
            g_bar_count = 0;
            __threadfence();
            g_bar_gen = gen + 1u;
        } else {
            while (g_bar_gen == gen) __nanosleep(32);
        }
    }
    __syncthreads();
}

// ---------------------------------------------------------------------------
__device__ __forceinline__ void split1(float v, unsigned short& h, unsigned short& l) {
    __nv_bfloat16 hb = __float2bfloat16(v);
    float r = v - __bfloat162float(hb);
    __nv_bfloat16 lb = __float2bfloat16(r);
    h = __bfloat16_as_ushort(hb);
    l = __bfloat16_as_ushort(lb);
}

// mma.sync m16n8k16 row.col f32.bf16.bf16.f32 (portable, sm_80+)
__device__ __forceinline__ void mma_bf16(float* c, const uint32_t* a, const uint32_t* b) {
    asm volatile(
        "mma.sync.aligned.m16n8k16.row.col.f32.bf16.bf16.f32 "
        "{%0,%1,%2,%3}, {%4,%5,%6,%7}, {%8,%9}, {%0,%1,%2,%3};"
        : "+f"(c[0]), "+f"(c[1]), "+f"(c[2]), "+f"(c[3])
        : "r"(a[0]), "r"(a[1]), "r"(a[2]), "r"(a[3]), "r"(b[0]), "r"(b[1]));
}

// ---------------------------------------------------------------------------
// x[b][t][i] -> hi/lo bf16 [t*B+b][i]
// ---------------------------------------------------------------------------
__global__ void k_transpose_x(const float* __restrict__ x) {
    int row = blockIdx.x;               // t*B + b
    int t = row / B_;
    int b = row % B_;
    const float4* src = (const float4*)(x + ((size_t)b * S_ + t) * IN_);
    ushort4* dh = (ushort4*)(g_xh + (size_t)row * IN_);
    ushort4* dl = (ushort4*)(g_xl + (size_t)row * IN_);
    for (int i = threadIdx.x; i < IN_ / 4; i += blockDim.x) {
        float4 v = src[i];
        ushort4 h, l;
        split1(v.x, h.x, l.x);
        split1(v.y, h.y, l.y);
        split1(v.z, h.z, l.z);
        split1(v.w, h.w, l.w);
        dh[i] = h;
        dl[i] = l;
    }
}

// ---------------------------------------------------------------------------
// weight split: fp32 -> hi/lo bf16
// ---------------------------------------------------------------------------
__global__ void k_split(const float* __restrict__ src, int wsel, int n4) {
    int i = blockIdx.x * blockDim.x + threadIdx.x;
    if (i >= n4) return;
    unsigned short* hi;
    unsigned short* lo;
    switch (wsel) {
        case 0: hi = g_wzxh; lo = g_wzxl; break;
        case 1: hi = g_wrxh; lo = g_wrxl; break;
        case 2: hi = g_wgxh; lo = g_wgxl; break;
        default: hi = g_woh; lo = g_wol; break;
    }
    float4 v = ((const float4*)src)[i];
    ushort4 h, l;
    split1(v.x, h.x, l.x);
    split1(v.y, h.y, l.y);
    split1(v.z, h.z, l.z);
    split1(v.w, h.w, l.w);
    ((ushort4*)hi)[i] = h;
    ((ushort4*)lo)[i] = l;
}

// ---------------------------------------------------------------------------
// g_h[b][c] = h0[b][layer][c]
// ---------------------------------------------------------------------------
__global__ void k_load_h(const float* __restrict__ h0, int layer) {
    int idx = blockIdx.x * blockDim.x + threadIdx.x;
    int b = idx / H_;
    int c = idx % H_;
    g_h[idx] = h0[((size_t)b * L_ + layer) * H_ + c];
}

// ---------------------------------------------------------------------------
// HMMA split-bf16 GEMM: C[m][n] = sum_k A[m][k]*W[n][k] + bias[n]
//   Tile 128x64, BK=32, 8 warps (warp tile 32x32), 3-term split accumulate.
//   smem pitch 40 bf16 (20 words): fragment LDS pattern conflict-free.
//   permC=0 -> g_gx[m][col0+n];  permC=1 -> Cout[(b*S+t)*ldc + n], m=t*B+b.
// ---------------------------------------------------------------------------
#define HMP 40   /* bf16 per smem row (32 data + 8 pad); 20 b32 words */

__global__ void __launch_bounds__(256) k_hmma(
    int asel, int wsel, int woff,
    const float* __restrict__ bias, float* __restrict__ Cout,
    int ldc, int col0, int permC)
{
    __shared__ __align__(16) unsigned short As_h[128 * HMP];
    __shared__ __align__(16) unsigned short As_l[128 * HMP];
    __shared__ __align__(16) unsigned short Bs_h[64 * HMP];
    __shared__ __align__(16) unsigned short Bs_l[64 * HMP];

    const int tid = threadIdx.x;
    const int m0 = blockIdx.y * 128, n0 = blockIdx.x * 64;

    const unsigned short* Ah = asel ? g_seqh : g_xh;
    const unsigned short* Al = asel ? g_seql : g_xl;
    const unsigned short* Wh;
    const unsigned short* Wl;
    switch (wsel) {
        case 0: Wh = g_wzxh; Wl = g_wzxl; break;
        case 1: Wh = g_wrxh; Wl = g_wrxl; break;
        case 2: Wh = g_wgxh; Wl = g_wgxl; break;
        default: Wh = g_woh; Wl = g_wol; break;
    }
    Wh += woff; Wl += woff;

    // loader mapping: A: idx = 2*tid + i -> r=idx>>2, u=idx&3 (uint4 of 8 bf16)
    //                 B: idx = tid      -> r=idx>>2, u=idx&3
    const int ar0 = (2 * tid) >> 2,     au0 = (2 * tid) & 3;
    const int ar1 = (2 * tid + 1) >> 2, au1 = (2 * tid + 1) & 3;
    const int br  = tid >> 2,           bu  = tid & 3;

    // compute mapping
    const int warp = tid >> 5, lane = tid & 31;
    const int g = lane >> 2, tg = lane & 3;
    const int wm = warp >> 1, wn = warp & 1;  // warp tile: 32(m) x 32(n)

    float acc[2][4][4];
#pragma unroll
    for (int mt = 0; mt < 2; mt++)
#pragma unroll
        for (int nt = 0; nt < 4; nt++)
#pragma unroll
            for (int i = 0; i < 4; i++) acc[mt][nt][i] = 0.f;

    const uint32_t* Awh = (const uint32_t*)As_h;
    const uint32_t* Awl = (const uint32_t*)As_l;
    const uint32_t* Bwh = (const uint32_t*)Bs_h;
    const uint32_t* Bwl = (const uint32_t*)Bs_l;

    uint4 vah0, vah1, val0, val1, vbh, vbl;
    {
        vah0 = *(const uint4*)(Ah + (size_t)(m0 + ar0) * 1024 + au0 * 8);
        vah1 = *(const uint4*)(Ah + (size_t)(m0 + ar1) * 1024 + au1 * 8);
        val0 = *(const uint4*)(Al + (size_t)(m0 + ar0) * 1024 + au0 * 8);
        val1 = *(const uint4*)(Al + (size_t)(m0 + ar1) * 1024 + au1 * 8);
        vbh  = *(const uint4*)(Wh + (size_t)(n0 + br) * 1024 + bu * 8);
        vbl  = *(const uint4*)(Wl + (size_t)(n0 + br) * 1024 + bu * 8);
    }

    for (int kc = 0; kc < 32; kc++) {
        __syncthreads();   // previous compute done before smem overwrite
        *(uint4*)(As_h + ar0 * HMP + au0 * 8) = vah0;
        *(uint4*)(As_h + ar1 * HMP + au1 * 8) = vah1;
        *(uint4*)(As_l + ar0 * HMP + au0 * 8) = val0;
        *(uint4*)(As_l + ar1 * HMP + au1 * 8) = val1;
        *(uint4*)(Bs_h + br * HMP + bu * 8) = vbh;
        *(uint4*)(Bs_l + br * HMP + bu * 8) = vbl;
        if (kc + 1 < 32) {
            int ko = (kc + 1) * 32;
            vah0 = *(const uint4*)(Ah + (size_t)(m0 + ar0) * 1024 + ko + au0 * 8);
            vah1 = *(const uint4*)(Ah + (size_t)(m0 + ar1) * 1024 + ko + au1 * 8);
            val0 = *(const uint4*)(Al + (size_t)(m0 + ar0) * 1024 + ko + au0 * 8);
            val1 = *(const uint4*)(Al + (size_t)(m0 + ar1) * 1024 + ko + au1 * 8);
            vbh  = *(const uint4*)(Wh + (size_t)(n0 + br) * 1024 + ko + bu * 8);
            vbl  = *(const uint4*)(Wl + (size_t)(n0 + br) * 1024 + ko + bu * 8);
        }
        __syncthreads();

#pragma unroll
        for (int ks = 0; ks < 2; ks++) {
            const int kw = ks * 8 + tg;    // b32 word offset within row

            uint32_t ahf[2][4], alf[2][4];
#pragma unroll
            for (int mt = 0; mt < 2; mt++) {
                int rb = (wm * 32 + mt * 16 + g) * 20 + kw;
                ahf[mt][0] = Awh[rb];
                ahf[mt][1] = Awh[rb + 160];      // +8 rows
                ahf[mt][2] = Awh[rb + 4];        // +8 k (4 words)
                ahf[mt][3] = Awh[rb + 164];
                alf[mt][0] = Awl[rb];
                alf[mt][1] = Awl[rb + 160];
                alf[mt][2] = Awl[rb + 4];
                alf[mt][3] = Awl[rb + 164];
            }
            uint32_t bhf[4][2], blf[4][2];
#pragma unroll
            for (int nt = 0; nt < 4; nt++) {
                int rb = (wn * 32 + nt * 8 + g) * 20 + kw;
                bhf[nt][0] = Bwh[rb];
                bhf[nt][1] = Bwh[rb + 4];
                blf[nt][0] = Bwl[rb];
                blf[nt][1] = Bwl[rb + 4];
            }
#pragma unroll
            for (int mt = 0; mt < 2; mt++)
#pragma unroll
                for (int nt = 0; nt < 4; nt++) {
                    mma_bf16(acc[mt][nt], ahf[mt], bhf[nt]);
                    mma_bf16(acc[mt][nt], ahf[mt], blf[nt]);
                    mma_bf16(acc[mt][nt], alf[mt], bhf[nt]);
                }
        }
    }

    // epilogue: c0,c1 -> (row g, col 2tg,2tg+1); c2,c3 -> row g+8
#pragma unroll
    for (int mt = 0; mt < 2; mt++) {
#pragma unroll
        for (int nt = 0; nt < 4; nt++) {
            int mrow = m0 + wm * 32 + mt * 16 + g;
            int ncol = n0 + wn * 32 + nt * 8 + tg * 2;
            float bx = bias[ncol], by = bias[ncol + 1];
#pragma unroll
            for (int half = 0; half < 2; half++) {
                int m = mrow + half * 8;
                float2 o;
                o.x = acc[mt][nt][half * 2 + 0] + bx;
                o.y = acc[mt][nt][half * 2 + 1] + by;
                float* dst;
                if (permC) {
                    int b = m & (B_ - 1);
                    int t = m >> 5;
                    dst = Cout + ((size_t)b * S_ + t) * ldc + ncol;
                } else {
                    dst = g_gx + (size_t)m * ldc + col0 + ncol;
                }
                *(float2*)dst = o;
            }
        }
    }
}

// ---------------------------------------------------------------------------
// recurrence (R4-proven): load tile, weights in regs/smem, multireduce.
// ---------------------------------------------------------------------------
__device__ __forceinline__ void load_tile(const float* __restrict__ src,
                                          float* __restrict__ s_h) {
    const int warp = threadIdx.x >> 5;
    const int lane = threadIdx.x & 31;
#pragma unroll
    for (int io = 0; io < 4; io++) {
        float4 v[8];
#pragma unroll
        for (int iu = 0; iu < 8; iu++) {
            int b = io * 8 + iu;
            int kq = warp * 32 + lane;
            v[iu] = __ldcg(reinterpret_cast<const float4*>(src + (size_t)b * H_) + kq);
        }
#pragma unroll
        for (int iu = 0; iu < 8; iu++) {
            int b = io * 8 + iu;
            int kq = warp * 32 + lane;
            reinterpret_cast<float4*>(s_h + (size_t)b * PITCH)[kq] = v[iu];
        }
    }
}

__device__ __forceinline__ float warp_multireduce(float* a, int lane) {
#pragma unroll
    for (int off = 16; off >= 1; off >>= 1) {
#pragma unroll
        for (int b = 0; b < off; b++) {
            bool hi = (lane & off) != 0;
            float send = hi ? a[b] : a[b + off];
            float recv = __shfl_xor_sync(0xffffffffu, send, off);
            a[b] = (hi ? a[b + off] : a[b]) + recv;
        }
    }
    return a[0];
}

__device__ __forceinline__ float sigmoidf_(float x) {
    return 1.f / (1.f + expf(-x));
}

__global__ void __launch_bounds__(256, 1) k_gru_recur(
    const float* __restrict__ Wzh, const float* __restrict__ Wrh,
    const float* __restrict__ Wgh, int layer, float* __restrict__ hid_out)
{
    extern __shared__ float smemf[];
    float* s_h  = smemf;                    // [32][1024]
    float* s_wg = smemf + TILE_WORDS;       // [8][1024]

    const int warp = threadIdx.x >> 5;
    const int lane = threadIdx.x & 31;

    const int vc   = blockIdx.x * 16 + warp * 2;
    const int gate = vc >> 10;              // 0=z, 1=r
    const int c1   = vc & 1023;
    const float* Wb = gate ? Wrh : Wzh;
    const float* W0 = Wb + ((size_t)layer * H_ + c1) * H_;
    const float* W1 = W0 + H_;

    float4 w0r[8], w1r[8];
#pragma unroll
    for (int kc = 0; kc < 8; kc++) {
        w0r[kc] = reinterpret_cast<const float4*>(W0 + kc * 128)[lane];
        w1r[kc] = reinterpret_cast<const float4*>(W1 + kc * 128)[lane];
    }

    const int c2 = blockIdx.x * 8 + warp * 2;    // valid when warp < 4

    for (int cc = 0; cc < 8; cc++) {
        const float4* src = reinterpret_cast<const float4*>(
            Wgh + ((size_t)layer * H_ + blockIdx.x * 8 + cc) * H_);
        reinterpret_cast<float4*>(s_wg + cc * H_)[threadIdx.x] = src[threadIdx.x];
    }
    __syncthreads();

    for (int t = 0; t < S_; t++) {
        const size_t row = (size_t)t * B_ + lane;

        // ---- phase 1: z and r ----
        load_tile(g_h, s_h);
        float gx0 = __ldcg(&g_gx[row * N3_ + (gate ? H_ : 0) + c1]);
        float gx1 = __ldcg(&g_gx[row * N3_ + (gate ? H_ : 0) + c1 + 1]);
        __syncthreads();

        float accA[32], accB[32];
#pragma unroll
        for (int b = 0; b < 32; b++) { accA[b] = 0.f; accB[b] = 0.f; }
#pragma unroll
        for (int kc = 0; kc < 8; kc++) {
            const float4* hp = reinterpret_cast<const float4*>(s_h + kc * 128) + lane;
            float4 w0 = w0r[kc], w1 = w1r[kc];
#pragma unroll
            for (int b = 0; b < 32; b++) {
                float4 h4 = hp[b * 256];
                accA[b] = fmaf(h4.x, w0.x, accA[b]);
                accA[b] = fmaf(h4.y, w0.y, accA[b]);
                accA[b] = fmaf(h4.z, w0.z, accA[b]);
                accA[b] = fmaf(h4.w, w0.w, accA[b]);
                accB[b] = fmaf(h4.x, w1.x, accB[b]);
                accB[b] = fmaf(h4.y, w1.y, accB[b]);
                accB[b] = fmaf(h4.z, w1.z, accB[b]);
                accB[b] = fmaf(h4.w, w1.w, accB[b]);
            }
        }
        float v0 = warp_multireduce(accA, lane);
        float v1 = warp_multireduce(accB, lane);

        if (gate == 0) {
            g_z[lane * H_ + c1]     = sigmoidf_(v0 + gx0);
            g_z[lane * H_ + c1 + 1] = sigmoidf_(v1 + gx1);
        } else {
            float h0v = s_h[lane * PITCH + c1];
            float h1v = s_h[lane * PITCH + c1 + 1];
            g_rh[lane * H_ + c1]     = sigmoidf_(v0 + gx0) * h0v;
            g_rh[lane * H_ + c1 + 1] = sigmoidf_(v1 + gx1) * h1v;
        }

        grid_sync();

        // ---- phase 2: g and h update ----
        load_tile(g_rh, s_h);
        float gxg0 = 0.f, gxg1 = 0.f, hv0 = 0.f, hv1 = 0.f, zv0 = 0.f, zv1 = 0.f;
        if (warp < 4) {
            gxg0 = __ldcg(&g_gx[row * N3_ + 2 * H_ + c2]);
            gxg1 = __ldcg(&g_gx[row * N3_ + 2 * H_ + c2 + 1]);
            hv0  = g_h[lane * H_ + c2];
            hv1  = g_h[lane * H_ + c2 + 1];
            zv0  = __ldcg(&g_z[lane * H_ + c2]);
            zv1  = __ldcg(&g_z[lane * H_ + c2 + 1]);
        }
        __syncthreads();

        if (warp < 4) {
            float acc0[32], acc1[32];
#pragma unroll
            for (int b = 0; b < 32; b++) { acc0[b] = 0.f; acc1[b] = 0.f; }
#pragma unroll
            for (int kc = 0; kc < 8; kc++) {
                const float4* hp = reinterpret_cast<const float4*>(s_h + kc * 128) + lane;
                float4 wA = reinterpret_cast<const float4*>(s_wg + (warp * 2) * H_ + kc * 128)[lane];
                float4 wB = reinterpret_cast<const float4*>(s_wg + (warp * 2 + 1) * H_ + kc * 128)[lane];
#pragma unroll
                for (int b = 0; b < 32; b++) {
                    float4 h4 = hp[b * 256];
                    acc0[b] = fmaf(h4.x, wA.x, acc0[b]);
                    acc0[b] = fmaf(h4.y, wA.y, acc0[b]);
                    acc0[b] = fmaf(h4.z, wA.z, acc0[b]);
                    acc0[b] = fmaf(h4.w, wA.w, acc0[b]);
                    acc1[b] = fmaf(h4.x, wB.x, acc1[b]);
                    acc1[b] = fmaf(h4.y, wB.y, acc1[b]);
                    acc1[b] = fmaf(h4.z, wB.z, acc1[b]);
                    acc1[b] = fmaf(h4.w, wB.w, acc1[b]);
                }
            }
            float vg0 = warp_multireduce(acc0, lane);
            float vg1 = warp_multireduce(acc1, lane);

            float gv0 = tanhf(vg0 + gxg0);
            float gv1 = tanhf(vg1 + gxg1);
            float hn0 = fmaf(zv0, gv0 - hv0, hv0);
            float hn1 = fmaf(zv1, gv1 - hv1, hv1);

            g_h[lane * H_ + c2]     = hn0;
            g_h[lane * H_ + c2 + 1] = hn1;

            unsigned short sh0, sl0, sh1, sl1;
            split1(hn0, sh0, sl0);
            split1(hn1, sh1, sl1);
            g_seqh[row * H_ + c2]     = sh0;
            g_seql[row * H_ + c2]     = sl0;
            g_seqh[row * H_ + c2 + 1] = sh1;
            g_seql[row * H_ + c2 + 1] = sl1;

            if (hid_out && t == S_ - 1) {
                hid_out[((size_t)lane * L_ + layer) * H_ + c2]     = hn0;
                hid_out[((size_t)lane * L_ + layer) * H_ + c2 + 1] = hn1;
            }
        }

        grid_sync();
    }
}

// ---------------------------------------------------------------------------
// Launch
// ---------------------------------------------------------------------------
extern "C" void kernel_launch(void* const* d_in, const int* in_sizes, int n_in,
                              void* d_out, int out_size) {
    (void)in_sizes; (void)n_in;
    const float* x   = (const float*)d_in[0];
    const float* h0  = (const float*)d_in[1];
    const float* Wzx = (const float*)d_in[2];
    const float* bz  = (const float*)d_in[3];
    const float* Wzh = (const float*)d_in[4];
    const float* Wrx = (const float*)d_in[5];
    const float* br  = (const float*)d_in[6];
    const float* Wrh = (const float*)d_in[7];
    const float* Wgx = (const float*)d_in[8];
    const float* bg  = (const float*)d_in[9];
    const float* Wgh = (const float*)d_in[10];
    const float* Wo  = (const float*)d_in[11];
    const float* bo  = (const float*)d_in[12];

    float* out = (float*)d_out;
    float* y_out = out;                                  // [B,S,O]
    const long long need = (long long)B_ * S_ * OUT_ + (long long)B_ * L_ * H_;
    float* hid_out = ((long long)out_size >= need) ? out + (size_t)B_ * S_ * OUT_
                                                   : nullptr;

    cudaFuncSetAttribute(k_gru_recur,
        cudaFuncAttributeMaxDynamicSharedMemorySize, SMEM_BYTES);

    // operand prep
    k_transpose_x<<<M_, 256>>>(x);
    const int wbig4 = (L_ * H_ * IN_) / 4;   // 524288
    const int wout4 = (OUT_ * H_) / 4;       // 262144
    k_split<<<wbig4 / 256, 256>>>(Wzx, 0, wbig4);
    k_split<<<wbig4 / 256, 256>>>(Wrx, 1, wbig4);
    k_split<<<wbig4 / 256, 256>>>(Wgx, 2, wbig4);
    k_split<<<wout4 / 256, 256>>>(Wo, 3, wout4);

    dim3 tgrid(1024 / 64, M_ / 128);   // (16, 128)

    for (int layer = 0; layer < L_; layer++) {
        k_load_h<<<(B_ * H_) / 256, 256>>>(h0, layer);

        const int woff = layer * H_ * IN_;
        k_hmma<<<tgrid, 256>>>(layer, 0, woff, bz + (size_t)layer * H_,
                               nullptr, N3_, 0, 0);
        k_hmma<<<tgrid, 256>>>(layer, 1, woff, br + (size_t)layer * H_,
                               nullptr, N3_, H_, 0);
        k_hmma<<<tgrid, 256>>>(layer, 2, woff, bg + (size_t)layer * H_,
                               nullptr, N3_, 2 * H_, 0);

        k_gru_recur<<<NBLK, 256, SMEM_BYTES>>>(Wzh, Wrh, Wgh, layer, hid_out);
    }

    // output projection
    k_hmma<<<tgrid, 256>>>(1, 3, 0, bo, y_out, OUT_, 0, 1);
}

// round 8
// speedup vs baseline: 1.5664x; 1.3559x over previous
#include <cuda_runtime.h>
#include <cuda_bf16.h>
#include <math.h>
#include <stdint.h>

// ---------------------------------------------------------------------------
// MultilayerGRU: B=32, S=512, I=H=O=1024, L=2
// R8: recurrence on tensor cores (mma.sync bf16 hi/lo 3-term split, weights
//     resident in register fragments for all 512 steps). h carried as bf16
//     hi/lo in gmem + fp32 master for the gate update. Big GEMMs = R7 k_hmma.
// ---------------------------------------------------------------------------

#define B_  32
#define S_  512
#define IN_ 1024
#define H_  1024
#define OUT_ 1024
#define L_  2
#define M_  (B_ * S_)      /* 16384 */
#define N3_ (3 * H_)       /* 3072  */
#define NBLK 128

// ---------------- device scratch ------------------------------------------
__device__ float g_gx[(size_t)M_ * N3_];   // x-projections for current layer
__device__ float g_h[B_ * H_];             // fp32 master hidden state
__device__ float g_z[B_ * H_];             // z gate

__device__ __align__(16) unsigned short g_hh[B_ * H_],  g_hl[B_ * H_];   // h split
__device__ __align__(16) unsigned short g_rhh[B_ * H_], g_rhl[B_ * H_]; // r*h split

// bf16 hi/lo operand buffers
__device__ __align__(16) unsigned short g_xh[(size_t)M_ * IN_],  g_xl[(size_t)M_ * IN_];
__device__ __align__(16) unsigned short g_seqh[(size_t)M_ * H_], g_seql[(size_t)M_ * H_];
__device__ __align__(16) unsigned short g_wzxh[(size_t)L_ * H_ * IN_], g_wzxl[(size_t)L_ * H_ * IN_];
__device__ __align__(16) unsigned short g_wrxh[(size_t)L_ * H_ * IN_], g_wrxl[(size_t)L_ * H_ * IN_];
__device__ __align__(16) unsigned short g_wgxh[(size_t)L_ * H_ * IN_], g_wgxl[(size_t)L_ * H_ * IN_];
__device__ __align__(16) unsigned short g_woh[(size_t)OUT_ * H_],      g_wol[(size_t)OUT_ * H_];
__device__ __align__(16) unsigned short g_wzhh[(size_t)L_ * H_ * H_],  g_wzhl[(size_t)L_ * H_ * H_];
__device__ __align__(16) unsigned short g_wrhh[(size_t)L_ * H_ * H_],  g_wrhl[(size_t)L_ * H_ * H_];
__device__ __align__(16) unsigned short g_wghh[(size_t)L_ * H_ * H_],  g_wghl[(size_t)L_ * H_ * H_];

// grid barrier (generation-based; replay-safe)
__device__ unsigned g_bar_count = 0;
__device__ volatile unsigned g_bar_gen = 0;

__device__ __forceinline__ void grid_sync() {
    __syncthreads();
    if (threadIdx.x == 0) {
        __threadfence();
        unsigned gen = g_bar_gen;
        if (atomicAdd(&g_bar_count, 1u) == NBLK - 1u) {
            g_bar_count = 0;
            __threadfence();
            g_bar_gen = gen + 1u;
        } else {
            while (g_bar_gen == gen) __nanosleep(32);
        }
    }
    __syncthreads();
}

// ---------------------------------------------------------------------------
__device__ __forceinline__ void split1(float v, unsigned short& h, unsigned short& l) {
    __nv_bfloat16 hb = __float2bfloat16(v);
    float r = v - __bfloat162float(hb);
    __nv_bfloat16 lb = __float2bfloat16(r);
    h = __bfloat16_as_ushort(hb);
    l = __bfloat16_as_ushort(lb);
}

__device__ __forceinline__ float us2f(unsigned short u) {
    return __bfloat162float(__ushort_as_bfloat16(u));
}

// mma.sync m16n8k16 row.col f32.bf16.bf16.f32
__device__ __forceinline__ void mma_bf16(float* c, const uint32_t* a, const uint32_t* b) {
    asm volatile(
        "mma.sync.aligned.m16n8k16.row.col.f32.bf16.bf16.f32 "
        "{%0,%1,%2,%3}, {%4,%5,%6,%7}, {%8,%9}, {%0,%1,%2,%3};"
        : "+f"(c[0]), "+f"(c[1]), "+f"(c[2]), "+f"(c[3])
        : "r"(a[0]), "r"(a[1]), "r"(a[2]), "r"(a[3]), "r"(b[0]), "r"(b[1]));
}

__device__ __forceinline__ float sigmoidf_(float x) {
    return 1.f / (1.f + expf(-x));
}

// ---------------------------------------------------------------------------
// x[b][t][i] -> hi/lo bf16 [t*B+b][i]
// ---------------------------------------------------------------------------
__global__ void k_transpose_x(const float* __restrict__ x) {
    int row = blockIdx.x;
    int t = row / B_;
    int b = row % B_;
    const float4* src = (const float4*)(x + ((size_t)b * S_ + t) * IN_);
    ushort4* dh = (ushort4*)(g_xh + (size_t)row * IN_);
    ushort4* dl = (ushort4*)(g_xl + (size_t)row * IN_);
    for (int i = threadIdx.x; i < IN_ / 4; i += blockDim.x) {
        float4 v = src[i];
        ushort4 h, l;
        split1(v.x, h.x, l.x);
        split1(v.y, h.y, l.y);
        split1(v.z, h.z, l.z);
        split1(v.w, h.w, l.w);
        dh[i] = h;
        dl[i] = l;
    }
}

// ---------------------------------------------------------------------------
// weight split: fp32 -> hi/lo bf16
// ---------------------------------------------------------------------------
__global__ void k_split(const float* __restrict__ src, int wsel, int n4) {
    int i = blockIdx.x * blockDim.x + threadIdx.x;
    if (i >= n4) return;
    unsigned short* hi;
    unsigned short* lo;
    switch (wsel) {
        case 0: hi = g_wzxh; lo = g_wzxl; break;
        case 1: hi = g_wrxh; lo = g_wrxl; break;
        case 2: hi = g_wgxh; lo = g_wgxl; break;
        case 3: hi = g_woh;  lo = g_wol;  break;
        case 4: hi = g_wzhh; lo = g_wzhl; break;
        case 5: hi = g_wrhh; lo = g_wrhl; break;
        default: hi = g_wghh; lo = g_wghl; break;
    }
    float4 v = ((const float4*)src)[i];
    ushort4 h, l;
    split1(v.x, h.x, l.x);
    split1(v.y, h.y, l.y);
    split1(v.z, h.z, l.z);
    split1(v.w, h.w, l.w);
    ((ushort4*)hi)[i] = h;
    ((ushort4*)lo)[i] = l;
}

// ---------------------------------------------------------------------------
// k_prep: g_h / g_hh / g_hl from h0[b][layer][:]; reset barrier.
// ---------------------------------------------------------------------------
__global__ void k_prep(const float* __restrict__ h0, int layer) {
    int idx = blockIdx.x * blockDim.x + threadIdx.x;  // [0, B*H)
    if (idx == 0) { g_bar_count = 0; g_bar_gen = 0; }
    int b = idx / H_;
    int c = idx % H_;
    float v = h0[((size_t)b * L_ + layer) * H_ + c];
    g_h[idx] = v;
    unsigned short h, l;
    split1(v, h, l);
    g_hh[idx] = h;
    g_hl[idx] = l;
}

// ---------------------------------------------------------------------------
// HMMA split-bf16 GEMM (unchanged from R7, proven).
// ---------------------------------------------------------------------------
#define HMP 40

__global__ void __launch_bounds__(256) k_hmma(
    int asel, int wsel, int woff,
    const float* __restrict__ bias, float* __restrict__ Cout,
    int ldc, int col0, int permC)
{
    __shared__ __align__(16) unsigned short As_h[128 * HMP];
    __shared__ __align__(16) unsigned short As_l[128 * HMP];
    __shared__ __align__(16) unsigned short Bs_h[64 * HMP];
    __shared__ __align__(16) unsigned short Bs_l[64 * HMP];

    const int tid = threadIdx.x;
    const int m0 = blockIdx.y * 128, n0 = blockIdx.x * 64;

    const unsigned short* Ah = asel ? g_seqh : g_xh;
    const unsigned short* Al = asel ? g_seql : g_xl;
    const unsigned short* Wh;
    const unsigned short* Wl;
    switch (wsel) {
        case 0: Wh = g_wzxh; Wl = g_wzxl; break;
        case 1: Wh = g_wrxh; Wl = g_wrxl; break;
        case 2: Wh = g_wgxh; Wl = g_wgxl; break;
        default: Wh = g_woh; Wl = g_wol; break;
    }
    Wh += woff; Wl += woff;

    const int ar0 = (2 * tid) >> 2,     au0 = (2 * tid) & 3;
    const int ar1 = (2 * tid + 1) >> 2, au1 = (2 * tid + 1) & 3;
    const int br  = tid >> 2,           bu  = tid & 3;

    const int warp = tid >> 5, lane = tid & 31;
    const int g = lane >> 2, tg = lane & 3;
    const int wm = warp >> 1, wn = warp & 1;

    float acc[2][4][4];
#pragma unroll
    for (int mt = 0; mt < 2; mt++)
#pragma unroll
        for (int nt = 0; nt < 4; nt++)
#pragma unroll
            for (int i = 0; i < 4; i++) acc[mt][nt][i] = 0.f;

    const uint32_t* Awh = (const uint32_t*)As_h;
    const uint32_t* Awl = (const uint32_t*)As_l;
    const uint32_t* Bwh = (const uint32_t*)Bs_h;
    const uint32_t* Bwl = (const uint32_t*)Bs_l;

    uint4 vah0, vah1, val0, val1, vbh, vbl;
    vah0 = *(const uint4*)(Ah + (size_t)(m0 + ar0) * 1024 + au0 * 8);
    vah1 = *(const uint4*)(Ah + (size_t)(m0 + ar1) * 1024 + au1 * 8);
    val0 = *(const uint4*)(Al + (size_t)(m0 + ar0) * 1024 + au0 * 8);
    val1 = *(const uint4*)(Al + (size_t)(m0 + ar1) * 1024 + au1 * 8);
    vbh  = *(const uint4*)(Wh + (size_t)(n0 + br) * 1024 + bu * 8);
    vbl  = *(const uint4*)(Wl + (size_t)(n0 + br) * 1024 + bu * 8);

    for (int kc = 0; kc < 32; kc++) {
        __syncthreads();
        *(uint4*)(As_h + ar0 * HMP + au0 * 8) = vah0;
        *(uint4*)(As_h + ar1 * HMP + au1 * 8) = vah1;
        *(uint4*)(As_l + ar0 * HMP + au0 * 8) = val0;
        *(uint4*)(As_l + ar1 * HMP + au1 * 8) = val1;
        *(uint4*)(Bs_h + br * HMP + bu * 8) = vbh;
        *(uint4*)(Bs_l + br * HMP + bu * 8) = vbl;
        if (kc + 1 < 32) {
            int ko = (kc + 1) * 32;
            vah0 = *(const uint4*)(Ah + (size_t)(m0 + ar0) * 1024 + ko + au0 * 8);
            vah1 = *(const uint4*)(Ah + (size_t)(m0 + ar1) * 1024 + ko + au1 * 8);
            val0 = *(const uint4*)(Al + (size_t)(m0 + ar0) * 1024 + ko + au0 * 8);
            val1 = *(const uint4*)(Al + (size_t)(m0 + ar1) * 1024 + ko + au1 * 8);
            vbh  = *(const uint4*)(Wh + (size_t)(n0 + br) * 1024 + ko + bu * 8);
            vbl  = *(const uint4*)(Wl + (size_t)(n0 + br) * 1024 + ko + bu * 8);
        }
        __syncthreads();

#pragma unroll
        for (int ks = 0; ks < 2; ks++) {
            const int kw = ks * 8 + tg;
            uint32_t ahf[2][4], alf[2][4];
#pragma unroll
            for (int mt = 0; mt < 2; mt++) {
                int rb = (wm * 32 + mt * 16 + g) * 20 + kw;
                ahf[mt][0] = Awh[rb];
                ahf[mt][1] = Awh[rb + 160];
                ahf[mt][2] = Awh[rb + 4];
                ahf[mt][3] = Awh[rb + 164];
                alf[mt][0] = Awl[rb];
                alf[mt][1] = Awl[rb + 160];
                alf[mt][2] = Awl[rb + 4];
                alf[mt][3] = Awl[rb + 164];
            }
            uint32_t bhf[4][2], blf[4][2];
#pragma unroll
            for (int nt = 0; nt < 4; nt++) {
                int rb = (wn * 32 + nt * 8 + g) * 20 + kw;
                bhf[nt][0] = Bwh[rb];
                bhf[nt][1] = Bwh[rb + 4];
                blf[nt][0] = Bwl[rb];
                blf[nt][1] = Bwl[rb + 4];
            }
#pragma unroll
            for (int mt = 0; mt < 2; mt++)
#pragma unroll
                for (int nt = 0; nt < 4; nt++) {
                    mma_bf16(acc[mt][nt], ahf[mt], bhf[nt]);
                    mma_bf16(acc[mt][nt], ahf[mt], blf[nt]);
                    mma_bf16(acc[mt][nt], alf[mt], bhf[nt]);
                }
        }
    }

#pragma unroll
    for (int mt = 0; mt < 2; mt++) {
#pragma unroll
        for (int nt = 0; nt < 4; nt++) {
            int mrow = m0 + wm * 32 + mt * 16 + g;
            int ncol = n0 + wn * 32 + nt * 8 + tg * 2;
            float bx = bias[ncol], by = bias[ncol + 1];
#pragma unroll
            for (int half = 0; half < 2; half++) {
                int m = mrow + half * 8;
                float2 o;
                o.x = acc[mt][nt][half * 2 + 0] + bx;
                o.y = acc[mt][nt][half * 2 + 1] + by;
                float* dst;
                if (permC) {
                    int b = m & (B_ - 1);
                    int t = m >> 5;
                    dst = Cout + ((size_t)b * S_ + t) * ldc + ncol;
                } else {
                    dst = g_gx + (size_t)m * ldc + col0 + ncol;
                }
                *(float2*)dst = o;
            }
        }
    }
}

// ---------------------------------------------------------------------------
// Tensor-core recurrence.
//   smem tile: [32 rows][SW_PW b32 words] per split; SW_PW mod 32 == 4 makes
//   the fragment LDS pattern (bank = 4g+tg) conflict-free.
//   Phase 1: block owns 16 (z|r) cols: M=32, N=16, K split 8 warps x 128.
//   Phase 2: block owns 8 g cols:     M=32, N=8.
//   Weights live in register fragments for the whole launch.
// ---------------------------------------------------------------------------
#define SW_PW 516
#define TILE_B (32 * SW_PW * 4)            /* 66048 bytes per split buffer */
#define RED_STRIDE 18
#define RED_B (8 * 32 * RED_STRIDE * 4)    /* 18432 */
#define SMEMR (2 * TILE_B + RED_B)         /* 150528 */

__device__ __forceinline__ void stage_tile(
    const unsigned short* __restrict__ gh, const unsigned short* __restrict__ gl,
    uint32_t* __restrict__ sh, uint32_t* __restrict__ sl)
{
    const int tid = threadIdx.x;
#pragma unroll 4
    for (int it = 0; it < 16; it++) {
        int idx = tid + 256 * it;          // 0..4095 over 32 rows x 128 uint4
        int row = idx >> 7;
        int u = idx & 127;
        uint4 v = __ldcg((const uint4*)(gh + (size_t)row * H_) + u);
        uint4 w = __ldcg((const uint4*)(gl + (size_t)row * H_) + u);
        *(uint4*)(sh + row * SW_PW + u * 4) = v;
        *(uint4*)(sl + row * SW_PW + u * 4) = w;
    }
}

__global__ void __launch_bounds__(256, 1) k_gru_recur(
    int layer, float* __restrict__ hid_out)
{
    extern __shared__ char smem[];
    uint32_t* s_hh = (uint32_t*)smem;                     // [32][SW_PW]
    uint32_t* s_hl = (uint32_t*)(smem + TILE_B);
    float*    red  = (float*)(smem + 2 * TILE_B);         // [8][32][18]

    const int tid = threadIdx.x;
    const int warp = tid >> 5, lane = tid & 31;
    const int g = lane >> 2, tg = lane & 3;

    // ---- ownership ----
    const int vc   = blockIdx.x * 16;       // [0,2048)
    const int gate = vc >> 10;               // 0=z, 1=r
    const int c1   = vc & 1023;              // 16 cols
    const int goff = gate ? H_ : 0;
    const int cg0  = blockIdx.x * 8;         // phase-2 cols

    const size_t lw = (size_t)layer * H_ * H_;

    // ---- resident weight fragments ----
    uint32_t w1h[2][8][2], w1l[2][8][2];     // phase 1: 2 n-tiles x 8 k-steps
    uint32_t w2h[8][2],    w2l[8][2];        // phase 2: 1 n-tile  x 8 k-steps
    {
        const unsigned short* W1h = gate ? g_wrhh : g_wzhh;
        const unsigned short* W1l = gate ? g_wrhl : g_wzhl;
#pragma unroll
        for (int nt = 0; nt < 2; nt++) {
#pragma unroll
            for (int ks = 0; ks < 8; ks++) {
                int row = c1 + nt * 8 + g;
                int kw = warp * 64 + ks * 8 + tg;
                const uint32_t* wr = (const uint32_t*)(W1h + lw + (size_t)row * H_);
                w1h[nt][ks][0] = wr[kw];
                w1h[nt][ks][1] = wr[kw + 4];
                const uint32_t* wr2 = (const uint32_t*)(W1l + lw + (size_t)row * H_);
                w1l[nt][ks][0] = wr2[kw];
                w1l[nt][ks][1] = wr2[kw + 4];
            }
        }
#pragma unroll
        for (int ks = 0; ks < 8; ks++) {
            int row = cg0 + g;
            int kw = warp * 64 + ks * 8 + tg;
            const uint32_t* wr = (const uint32_t*)(g_wghh + lw + (size_t)row * H_);
            w2h[ks][0] = wr[kw];
            w2h[ks][1] = wr[kw + 4];
            const uint32_t* wr2 = (const uint32_t*)(g_wghl + lw + (size_t)row * H_);
            w2l[ks][0] = wr2[kw];
            w2l[ks][1] = wr2[kw + 4];
        }
    }

    for (int t = 0; t < S_; t++) {
        // ================= phase 1: z and r =================
        stage_tile(g_hh, g_hl, s_hh, s_hl);
        __syncthreads();

        float acc[2][2][4];
#pragma unroll
        for (int mt = 0; mt < 2; mt++)
#pragma unroll
            for (int nt = 0; nt < 2; nt++)
#pragma unroll
                for (int i = 0; i < 4; i++) acc[mt][nt][i] = 0.f;

#pragma unroll
        for (int ks = 0; ks < 8; ks++) {
            const int kw = warp * 64 + ks * 8 + tg;
            uint32_t ah[2][4], al[2][4];
#pragma unroll
            for (int mt = 0; mt < 2; mt++) {
                const uint32_t* b0 = s_hh + (mt * 16 + g) * SW_PW;
                const uint32_t* b1 = b0 + 8 * SW_PW;
                ah[mt][0] = b0[kw];
                ah[mt][1] = b1[kw];
                ah[mt][2] = b0[kw + 4];
                ah[mt][3] = b1[kw + 4];
                const uint32_t* c0 = s_hl + (mt * 16 + g) * SW_PW;
                const uint32_t* c1p = c0 + 8 * SW_PW;
                al[mt][0] = c0[kw];
                al[mt][1] = c1p[kw];
                al[mt][2] = c0[kw + 4];
                al[mt][3] = c1p[kw + 4];
            }
#pragma unroll
            for (int mt = 0; mt < 2; mt++)
#pragma unroll
                for (int nt = 0; nt < 2; nt++) {
                    mma_bf16(acc[mt][nt], ah[mt], w1h[nt][ks]);
                    mma_bf16(acc[mt][nt], ah[mt], w1l[nt][ks]);
                    mma_bf16(acc[mt][nt], al[mt], w1h[nt][ks]);
                }
        }

        // cross-warp K reduction
#pragma unroll
        for (int mt = 0; mt < 2; mt++)
#pragma unroll
            for (int nt = 0; nt < 2; nt++)
#pragma unroll
                for (int i = 0; i < 4; i++) {
                    int row = mt * 16 + g + (i >> 1) * 8;
                    int col = nt * 8 + tg * 2 + (i & 1);
                    red[(warp * 32 + row) * RED_STRIDE + col] = acc[mt][nt][i];
                }
        __syncthreads();

#pragma unroll
        for (int o = tid; o < 512; o += 256) {
            int b = o >> 4, col = o & 15;
            float v = 0.f;
#pragma unroll
            for (int w = 0; w < 8; w++) v += red[(w * 32 + b) * RED_STRIDE + col];
            int j = c1 + col;
            float gx = __ldcg(&g_gx[((size_t)t * B_ + b) * N3_ + goff + j]);
            float sval = sigmoidf_(v + gx);
            if (gate == 0) {
                g_z[b * H_ + j] = sval;
            } else {
                const unsigned short* hr = (const unsigned short*)(s_hh + (size_t)b * SW_PW);
                const unsigned short* lr = (const unsigned short*)(s_hl + (size_t)b * SW_PW);
                float h = us2f(hr[j]) + us2f(lr[j]);
                float rh = sval * h;
                unsigned short rhh, rhl;
                split1(rh, rhh, rhl);
                g_rhh[b * H_ + j] = rhh;
                g_rhl[b * H_ + j] = rhl;
            }
        }

        grid_sync();

        // ================= phase 2: g and h update =================
        stage_tile(g_rhh, g_rhl, s_hh, s_hl);
        __syncthreads();

        float acc2[2][4];
#pragma unroll
        for (int mt = 0; mt < 2; mt++)
#pragma unroll
            for (int i = 0; i < 4; i++) acc2[mt][i] = 0.f;

#pragma unroll
        for (int ks = 0; ks < 8; ks++) {
            const int kw = warp * 64 + ks * 8 + tg;
            uint32_t ah[2][4], al[2][4];
#pragma unroll
            for (int mt = 0; mt < 2; mt++) {
                const uint32_t* b0 = s_hh + (mt * 16 + g) * SW_PW;
                const uint32_t* b1 = b0 + 8 * SW_PW;
                ah[mt][0] = b0[kw];
                ah[mt][1] = b1[kw];
                ah[mt][2] = b0[kw + 4];
                ah[mt][3] = b1[kw + 4];
                const uint32_t* c0 = s_hl + (mt * 16 + g) * SW_PW;
                const uint32_t* c1p = c0 + 8 * SW_PW;
                al[mt][0] = c0[kw];
                al[mt][1] = c1p[kw];
                al[mt][2] = c0[kw + 4];
                al[mt][3] = c1p[kw + 4];
            }
#pragma unroll
            for (int mt = 0; mt < 2; mt++) {
                mma_bf16(acc2[mt], ah[mt], w2h[ks]);
                mma_bf16(acc2[mt], ah[mt], w2l[ks]);
                mma_bf16(acc2[mt], al[mt], w2h[ks]);
            }
        }

#pragma unroll
        for (int mt = 0; mt < 2; mt++)
#pragma unroll
            for (int i = 0; i < 4; i++) {
                int row = mt * 16 + g + (i >> 1) * 8;
                int col = tg * 2 + (i & 1);
                red[(warp * 32 + row) * RED_STRIDE + col] = acc2[mt][i];
            }
        __syncthreads();

        {
            int b = tid >> 3, col = tid & 7;
            float v = 0.f;
#pragma unroll
            for (int w = 0; w < 8; w++) v += red[(w * 32 + b) * RED_STRIDE + col];
            int j = cg0 + col;
            size_t row = (size_t)t * B_ + b;
            float gxg = __ldcg(&g_gx[row * N3_ + 2 * H_ + j]);
            float zv = __ldcg(&g_z[b * H_ + j]);
            float hv = g_h[b * H_ + j];
            float gv = tanhf(v + gxg);
            float hn = fmaf(zv, gv - hv, hv);

            g_h[b * H_ + j] = hn;
            unsigned short hh, hl;
            split1(hn, hh, hl);
            g_hh[b * H_ + j] = hh;
            g_hl[b * H_ + j] = hl;
            g_seqh[row * H_ + j] = hh;
            g_seql[row * H_ + j] = hl;
            if (hid_out && t == S_ - 1)
                hid_out[((size_t)b * L_ + layer) * H_ + j] = hn;
        }

        grid_sync();
    }
}

// ---------------------------------------------------------------------------
// Launch
// ---------------------------------------------------------------------------
extern "C" void kernel_launch(void* const* d_in, const int* in_sizes, int n_in,
                              void* d_out, int out_size) {
    (void)in_sizes; (void)n_in;
    const float* x   = (const float*)d_in[0];
    const float* h0  = (const float*)d_in[1];
    const float* Wzx = (const float*)d_in[2];
    const float* bz  = (const float*)d_in[3];
    const float* Wzh = (const float*)d_in[4];
    const float* Wrx = (const float*)d_in[5];
    const float* br  = (const float*)d_in[6];
    const float* Wrh = (const float*)d_in[7];
    const float* Wgx = (const float*)d_in[8];
    const float* bg  = (const float*)d_in[9];
    const float* Wgh = (const float*)d_in[10];
    const float* Wo  = (const float*)d_in[11];
    const float* bo  = (const float*)d_in[12];

    float* out = (float*)d_out;
    float* y_out = out;
    const long long need = (long long)B_ * S_ * OUT_ + (long long)B_ * L_ * H_;
    float* hid_out = ((long long)out_size >= need) ? out + (size_t)B_ * S_ * OUT_
                                                   : nullptr;

    cudaFuncSetAttribute(k_gru_recur,
        cudaFuncAttributeMaxDynamicSharedMemorySize, SMEMR);

    // operand prep
    k_transpose_x<<<M_, 256>>>(x);
    const int wbig4 = (L_ * H_ * IN_) / 4;   // 524288
    const int wout4 = (OUT_ * H_) / 4;       // 262144
    k_split<<<wbig4 / 256, 256>>>(Wzx, 0, wbig4);
    k_split<<<wbig4 / 256, 256>>>(Wrx, 1, wbig4);
    k_split<<<wbig4 / 256, 256>>>(Wgx, 2, wbig4);
    k_split<<<wout4 / 256, 256>>>(Wo, 3, wout4);
    k_split<<<wbig4 / 256, 256>>>(Wzh, 4, wbig4);
    k_split<<<wbig4 / 256, 256>>>(Wrh, 5, wbig4);
    k_split<<<wbig4 / 256, 256>>>(Wgh, 6, wbig4);

    dim3 tgrid(1024 / 64, M_ / 128);   // (16, 128)

    for (int layer = 0; layer < L_; layer++) {
        k_prep<<<(B_ * H_) / 256, 256>>>(h0, layer);

        const int woff = layer * H_ * IN_;
        k_hmma<<<tgrid, 256>>>(layer, 0, woff, bz + (size_t)layer * H_,
                               nullptr, N3_, 0, 0);
        k_hmma<<<tgrid, 256>>>(layer, 1, woff, br + (size_t)layer * H_,
                               nullptr, N3_, H_, 0);
        k_hmma<<<tgrid, 256>>>(layer, 2, woff, bg + (size_t)layer * H_,
                               nullptr, N3_, 2 * H_, 0);

        k_gru_recur<<<NBLK, 256, SMEMR>>>(layer, hid_out);
    }

    // output projection
    k_hmma<<<tgrid, 256>>>(1, 3, 0, bo, y_out, OUT_, 0, 1);
}

// round 9
// speedup vs baseline: 1.8966x; 1.2108x over previous
#include <cuda_runtime.h>
#include <cuda_bf16.h>
#include <cuda_fp16.h>
#include <math.h>
#include <stdint.h>

// ---------------------------------------------------------------------------
// MultilayerGRU: B=32, S=512, I=H=O=1024, L=2
// R9: recurrence exchange in fp16 — phase 1 (z,r) single-fp16 h tile + single
//     fp16 weights (1 MMA term); phase 2 (g) fp16 hi/lo r*h + fp16 hi/lo Wgh
//     (3 terms, ~2^-24 residual). Halves phase-1 broadcast bytes, cuts MMA 3x.
//     fp32 master h kept for exact updates. Big GEMMs = proven bf16 k_hmma.
// ---------------------------------------------------------------------------

#define B_  32
#define S_  512
#define IN_ 1024
#define H_  1024
#define OUT_ 1024
#define L_  2
#define M_  (B_ * S_)      /* 16384 */
#define N3_ (3 * H_)       /* 3072  */
#define NBLK 128

// ---------------- device scratch ------------------------------------------
__device__ float g_gx[(size_t)M_ * N3_];   // x-projections for current layer
__device__ float g_h[B_ * H_];             // fp32 master hidden state
__device__ float g_z[B_ * H_];             // z gate

__device__ __align__(16) unsigned short g_hf[B_ * H_];                  // h fp16
__device__ __align__(16) unsigned short g_rhh[B_ * H_], g_rhl[B_ * H_]; // r*h fp16 hi/lo

// bf16 hi/lo operand buffers (GEMM path)
__device__ __align__(16) unsigned short g_xh[(size_t)M_ * IN_],  g_xl[(size_t)M_ * IN_];
__device__ __align__(16) unsigned short g_seqh[(size_t)M_ * H_], g_seql[(size_t)M_ * H_];
__device__ __align__(16) unsigned short g_wzxh[(size_t)L_ * H_ * IN_], g_wzxl[(size_t)L_ * H_ * IN_];
__device__ __align__(16) unsigned short g_wrxh[(size_t)L_ * H_ * IN_], g_wrxl[(size_t)L_ * H_ * IN_];
__device__ __align__(16) unsigned short g_wgxh[(size_t)L_ * H_ * IN_], g_wgxl[(size_t)L_ * H_ * IN_];
__device__ __align__(16) unsigned short g_woh[(size_t)OUT_ * H_],      g_wol[(size_t)OUT_ * H_];

// fp16 recurrence weights
__device__ __align__(16) unsigned short g_wzhf[(size_t)L_ * H_ * H_];
__device__ __align__(16) unsigned short g_wrhf[(size_t)L_ * H_ * H_];
__device__ __align__(16) unsigned short g_wghh16[(size_t)L_ * H_ * H_];
__device__ __align__(16) unsigned short g_wghl16[(size_t)L_ * H_ * H_];

// grid barrier (generation-based; replay-safe)
__device__ unsigned g_bar_count = 0;
__device__ volatile unsigned g_bar_gen = 0;

__device__ __forceinline__ void grid_sync() {
    __syncthreads();
    if (threadIdx.x == 0) {
        __threadfence();
        unsigned gen = g_bar_gen;
        if (atomicAdd(&g_bar_count, 1u) == NBLK - 1u) {
            g_bar_count = 0;
            __threadfence();
            g_bar_gen = gen + 1u;
        } else {
            while (g_bar_gen == gen) { }
        }
    }
    __syncthreads();
}

// ---------------------------------------------------------------------------
__device__ __forceinline__ void split1(float v, unsigned short& h, unsigned short& l) {
    __nv_bfloat16 hb = __float2bfloat16(v);
    float r = v - __bfloat162float(hb);
    __nv_bfloat16 lb = __float2bfloat16(r);
    h = __bfloat16_as_ushort(hb);
    l = __bfloat16_as_ushort(lb);
}

__device__ __forceinline__ void split16(float v, unsigned short& h, unsigned short& l) {
    __half hh = __float2half(v);
    float r = v - __half2float(hh);
    h = __half_as_ushort(hh);
    l = __half_as_ushort(__float2half(r));
}

// mma.sync m16n8k16 row.col, bf16 and fp16 flavors
__device__ __forceinline__ void mma_bf16(float* c, const uint32_t* a, const uint32_t* b) {
    asm volatile(
        "mma.sync.aligned.m16n8k16.row.col.f32.bf16.bf16.f32 "
        "{%0,%1,%2,%3}, {%4,%5,%6,%7}, {%8,%9}, {%0,%1,%2,%3};"
        : "+f"(c[0]), "+f"(c[1]), "+f"(c[2]), "+f"(c[3])
        : "r"(a[0]), "r"(a[1]), "r"(a[2]), "r"(a[3]), "r"(b[0]), "r"(b[1]));
}

__device__ __forceinline__ void mma_f16(float* c, const uint32_t* a, const uint32_t* b) {
    asm volatile(
        "mma.sync.aligned.m16n8k16.row.col.f32.f16.f16.f32 "
        "{%0,%1,%2,%3}, {%4,%5,%6,%7}, {%8,%9}, {%0,%1,%2,%3};"
        : "+f"(c[0]), "+f"(c[1]), "+f"(c[2]), "+f"(c[3])
        : "r"(a[0]), "r"(a[1]), "r"(a[2]), "r"(a[3]), "r"(b[0]), "r"(b[1]));
}

__device__ __forceinline__ float sigmoidf_(float x) {
    return 1.f / (1.f + expf(-x));
}

// ---------------------------------------------------------------------------
// x[b][t][i] -> hi/lo bf16 [t*B+b][i]
// ---------------------------------------------------------------------------
__global__ void k_transpose_x(const float* __restrict__ x) {
    int row = blockIdx.x;
    int t = row / B_;
    int b = row % B_;
    const float4* src = (const float4*)(x + ((size_t)b * S_ + t) * IN_);
    ushort4* dh = (ushort4*)(g_xh + (size_t)row * IN_);
    ushort4* dl = (ushort4*)(g_xl + (size_t)row * IN_);
    for (int i = threadIdx.x; i < IN_ / 4; i += blockDim.x) {
        float4 v = src[i];
        ushort4 h, l;
        split1(v.x, h.x, l.x);
        split1(v.y, h.y, l.y);
        split1(v.z, h.z, l.z);
        split1(v.w, h.w, l.w);
        dh[i] = h;
        dl[i] = l;
    }
}

// ---------------------------------------------------------------------------
// weight splits
// ---------------------------------------------------------------------------
__global__ void k_split(const float* __restrict__ src, int wsel, int n4) {
    int i = blockIdx.x * blockDim.x + threadIdx.x;
    if (i >= n4) return;
    unsigned short* hi;
    unsigned short* lo;
    switch (wsel) {
        case 0: hi = g_wzxh; lo = g_wzxl; break;
        case 1: hi = g_wrxh; lo = g_wrxl; break;
        case 2: hi = g_wgxh; lo = g_wgxl; break;
        default: hi = g_woh;  lo = g_wol; break;
    }
    float4 v = ((const float4*)src)[i];
    ushort4 h, l;
    split1(v.x, h.x, l.x);
    split1(v.y, h.y, l.y);
    split1(v.z, h.z, l.z);
    split1(v.w, h.w, l.w);
    ((ushort4*)hi)[i] = h;
    ((ushort4*)lo)[i] = l;
}

__global__ void k_split16(const float* __restrict__ src, int wsel, int n4) {
    int i = blockIdx.x * blockDim.x + threadIdx.x;
    if (i >= n4) return;
    float4 v = ((const float4*)src)[i];
    if (wsel < 2) {
        unsigned short* hi = wsel ? g_wrhf : g_wzhf;
        ushort4 h;
        h.x = __half_as_ushort(__float2half(v.x));
        h.y = __half_as_ushort(__float2half(v.y));
        h.z = __half_as_ushort(__float2half(v.z));
        h.w = __half_as_ushort(__float2half(v.w));
        ((ushort4*)hi)[i] = h;
    } else {
        ushort4 h, l;
        split16(v.x, h.x, l.x);
        split16(v.y, h.y, l.y);
        split16(v.z, h.z, l.z);
        split16(v.w, h.w, l.w);
        ((ushort4*)g_wghh16)[i] = h;
        ((ushort4*)g_wghl16)[i] = l;
    }
}

// ---------------------------------------------------------------------------
// k_prep: g_h / g_hf from h0[b][layer][:]; reset barrier.
// ---------------------------------------------------------------------------
__global__ void k_prep(const float* __restrict__ h0, int layer) {
    int idx = blockIdx.x * blockDim.x + threadIdx.x;  // [0, B*H)
    if (idx == 0) { g_bar_count = 0; g_bar_gen = 0; }
    int b = idx / H_;
    int c = idx % H_;
    float v = h0[((size_t)b * L_ + layer) * H_ + c];
    g_h[idx] = v;
    g_hf[idx] = __half_as_ushort(__float2half(v));
}

// ---------------------------------------------------------------------------
// HMMA split-bf16 GEMM (unchanged, proven).
// ---------------------------------------------------------------------------
#define HMP 40

__global__ void __launch_bounds__(256) k_hmma(
    int asel, int wsel, int woff,
    const float* __restrict__ bias, float* __restrict__ Cout,
    int ldc, int col0, int permC)
{
    __shared__ __align__(16) unsigned short As_h[128 * HMP];
    __shared__ __align__(16) unsigned short As_l[128 * HMP];
    __shared__ __align__(16) unsigned short Bs_h[64 * HMP];
    __shared__ __align__(16) unsigned short Bs_l[64 * HMP];

    const int tid = threadIdx.x;
    const int m0 = blockIdx.y * 128, n0 = blockIdx.x * 64;

    const unsigned short* Ah = asel ? g_seqh : g_xh;
    const unsigned short* Al = asel ? g_seql : g_xl;
    const unsigned short* Wh;
    const unsigned short* Wl;
    switch (wsel) {
        case 0: Wh = g_wzxh; Wl = g_wzxl; break;
        case 1: Wh = g_wrxh; Wl = g_wrxl; break;
        case 2: Wh = g_wgxh; Wl = g_wgxl; break;
        default: Wh = g_woh; Wl = g_wol; break;
    }
    Wh += woff; Wl += woff;

    const int ar0 = (2 * tid) >> 2,     au0 = (2 * tid) & 3;
    const int ar1 = (2 * tid + 1) >> 2, au1 = (2 * tid + 1) & 3;
    const int br  = tid >> 2,           bu  = tid & 3;

    const int warp = tid >> 5, lane = tid & 31;
    const int g = lane >> 2, tg = lane & 3;
    const int wm = warp >> 1, wn = warp & 1;

    float acc[2][4][4];
#pragma unroll
    for (int mt = 0; mt < 2; mt++)
#pragma unroll
        for (int nt = 0; nt < 4; nt++)
#pragma unroll
            for (int i = 0; i < 4; i++) acc[mt][nt][i] = 0.f;

    const uint32_t* Awh = (const uint32_t*)As_h;
    const uint32_t* Awl = (const uint32_t*)As_l;
    const uint32_t* Bwh = (const uint32_t*)Bs_h;
    const uint32_t* Bwl = (const uint32_t*)Bs_l;

    uint4 vah0, vah1, val0, val1, vbh, vbl;
    vah0 = *(const uint4*)(Ah + (size_t)(m0 + ar0) * 1024 + au0 * 8);
    vah1 = *(const uint4*)(Ah + (size_t)(m0 + ar1) * 1024 + au1 * 8);
    val0 = *(const uint4*)(Al + (size_t)(m0 + ar0) * 1024 + au0 * 8);
    val1 = *(const uint4*)(Al + (size_t)(m0 + ar1) * 1024 + au1 * 8);
    vbh  = *(const uint4*)(Wh + (size_t)(n0 + br) * 1024 + bu * 8);
    vbl  = *(const uint4*)(Wl + (size_t)(n0 + br) * 1024 + bu * 8);

    for (int kc = 0; kc < 32; kc++) {
        __syncthreads();
        *(uint4*)(As_h + ar0 * HMP + au0 * 8) = vah0;
        *(uint4*)(As_h + ar1 * HMP + au1 * 8) = vah1;
        *(uint4*)(As_l + ar0 * HMP + au0 * 8) = val0;
        *(uint4*)(As_l + ar1 * HMP + au1 * 8) = val1;
        *(uint4*)(Bs_h + br * HMP + bu * 8) = vbh;
        *(uint4*)(Bs_l + br * HMP + bu * 8) = vbl;
        if (kc + 1 < 32) {
            int ko = (kc + 1) * 32;
            vah0 = *(const uint4*)(Ah + (size_t)(m0 + ar0) * 1024 + ko + au0 * 8);
            vah1 = *(const uint4*)(Ah + (size_t)(m0 + ar1) * 1024 + ko + au1 * 8);
            val0 = *(const uint4*)(Al + (size_t)(m0 + ar0) * 1024 + ko + au0 * 8);
            val1 = *(const uint4*)(Al + (size_t)(m0 + ar1) * 1024 + ko + au1 * 8);
            vbh  = *(const uint4*)(Wh + (size_t)(n0 + br) * 1024 + ko + bu * 8);
            vbl  = *(const uint4*)(Wl + (size_t)(n0 + br) * 1024 + ko + bu * 8);
        }
        __syncthreads();

#pragma unroll
        for (int ks = 0; ks < 2; ks++) {
            const int kw = ks * 8 + tg;
            uint32_t ahf[2][4], alf[2][4];
#pragma unroll
            for (int mt = 0; mt < 2; mt++) {
                int rb = (wm * 32 + mt * 16 + g) * 20 + kw;
                ahf[mt][0] = Awh[rb];
                ahf[mt][1] = Awh[rb + 160];
                ahf[mt][2] = Awh[rb + 4];
                ahf[mt][3] = Awh[rb + 164];
                alf[mt][0] = Awl[rb];
                alf[mt][1] = Awl[rb + 160];
                alf[mt][2] = Awl[rb + 4];
                alf[mt][3] = Awl[rb + 164];
            }
            uint32_t bhf[4][2], blf[4][2];
#pragma unroll
            for (int nt = 0; nt < 4; nt++) {
                int rb = (wn * 32 + nt * 8 + g) * 20 + kw;
                bhf[nt][0] = Bwh[rb];
                bhf[nt][1] = Bwh[rb + 4];
                blf[nt][0] = Bwl[rb];
                blf[nt][1] = Bwl[rb + 4];
            }
#pragma unroll
            for (int mt = 0; mt < 2; mt++)
#pragma unroll
                for (int nt = 0; nt < 4; nt++) {
                    mma_bf16(acc[mt][nt], ahf[mt], bhf[nt]);
                    mma_bf16(acc[mt][nt], ahf[mt], blf[nt]);
                    mma_bf16(acc[mt][nt], alf[mt], bhf[nt]);
                }
        }
    }

#pragma unroll
    for (int mt = 0; mt < 2; mt++) {
#pragma unroll
        for (int nt = 0; nt < 4; nt++) {
            int mrow = m0 + wm * 32 + mt * 16 + g;
            int ncol = n0 + wn * 32 + nt * 8 + tg * 2;
            float bx = bias[ncol], by = bias[ncol + 1];
#pragma unroll
            for (int half = 0; half < 2; half++) {
                int m = mrow + half * 8;
                float2 o;
                o.x = acc[mt][nt][half * 2 + 0] + bx;
                o.y = acc[mt][nt][half * 2 + 1] + by;
                float* dst;
                if (permC) {
                    int b = m & (B_ - 1);
                    int t = m >> 5;
                    dst = Cout + ((size_t)b * S_ + t) * ldc + ncol;
                } else {
                    dst = g_gx + (size_t)m * ldc + col0 + ncol;
                }
                *(float2*)dst = o;
            }
        }
    }
}

// ---------------------------------------------------------------------------
// fp16 tensor-core recurrence.
//   tiles: [32 rows][SW_PW words], SW_PW mod 32 == 4 -> conflict-free frags.
//   Phase 1: 16 (z|r) cols/block, single-fp16 h and W (1 MMA term).
//   Phase 2: 8 g cols/block, fp16 hi/lo r*h and Wgh (3 MMA terms).
// ---------------------------------------------------------------------------
#define SW_PW 516
#define TILE_B (32 * SW_PW * 4)            /* 66048 bytes per tile buffer */
#define RED_STRIDE 18
#define RED_B (8 * 32 * RED_STRIDE * 4)    /* 18432 */
#define SMEMR (2 * TILE_B + RED_B)         /* 150528 */

// stage 32x1024 fp16 (512 words) from gmem into one smem tile
__device__ __forceinline__ void stage_one(
    const unsigned short* __restrict__ gsrc, uint32_t* __restrict__ s)
{
    const int tid = threadIdx.x;
#pragma unroll
    for (int rr = 0; rr < 2; rr++) {
        uint4 v[8];
#pragma unroll
        for (int it = 0; it < 8; it++) {
            int idx = tid + 256 * (rr * 8 + it);
            int row = idx >> 7;
            int u = idx & 127;
            v[it] = __ldcg((const uint4*)(gsrc + (size_t)row * H_) + u);
        }
#pragma unroll
        for (int it = 0; it < 8; it++) {
            int idx = tid + 256 * (rr * 8 + it);
            int row = idx >> 7;
            int u = idx & 127;
            *(uint4*)(s + row * SW_PW + u * 4) = v[it];
        }
    }
}

__device__ __forceinline__ void stage_two(
    const unsigned short* __restrict__ gh, const unsigned short* __restrict__ gl,
    uint32_t* __restrict__ sh, uint32_t* __restrict__ sl)
{
    const int tid = threadIdx.x;
#pragma unroll
    for (int rr = 0; rr < 4; rr++) {
        uint4 v[4], w[4];
#pragma unroll
        for (int it = 0; it < 4; it++) {
            int idx = tid + 256 * (rr * 4 + it);
            int row = idx >> 7;
            int u = idx & 127;
            v[it] = __ldcg((const uint4*)(gh + (size_t)row * H_) + u);
            w[it] = __ldcg((const uint4*)(gl + (size_t)row * H_) + u);
        }
#pragma unroll
        for (int it = 0; it < 4; it++) {
            int idx = tid + 256 * (rr * 4 + it);
            int row = idx >> 7;
            int u = idx & 127;
            *(uint4*)(sh + row * SW_PW + u * 4) = v[it];
            *(uint4*)(sl + row * SW_PW + u * 4) = w[it];
        }
    }
}

__global__ void __launch_bounds__(256, 1) k_gru_recur(
    int layer, float* __restrict__ hid_out)
{
    extern __shared__ char smem[];
    uint32_t* s_t0 = (uint32_t*)smem;                    // tile 0
    uint32_t* s_t1 = (uint32_t*)(smem + TILE_B);         // tile 1
    float*    red  = (float*)(smem + 2 * TILE_B);        // [8][32][18]

    const int tid = threadIdx.x;
    const int warp = tid >> 5, lane = tid & 31;
    const int g = lane >> 2, tg = lane & 3;

    // ---- ownership ----
    const int vc   = blockIdx.x * 16;        // [0,2048)
    const int gate = vc >> 10;               // 0=z, 1=r
    const int c1   = vc & 1023;
    const int goff = gate ? H_ : 0;
    const int cg0  = blockIdx.x * 8;         // phase-2 cols

    const size_t lw = (size_t)layer * H_ * H_;

    // ---- resident weight fragments ----
    uint32_t w1f[2][8][2];                   // phase 1: single fp16
    uint32_t w2h[8][2], w2l[8][2];           // phase 2: fp16 hi/lo
    {
        const unsigned short* W1 = gate ? g_wrhf : g_wzhf;
#pragma unroll
        for (int nt = 0; nt < 2; nt++)
#pragma unroll
            for (int ks = 0; ks < 8; ks++) {
                int row = c1 + nt * 8 + g;
                int kw = warp * 64 + ks * 8 + tg;
                const uint32_t* wr = (const uint32_t*)(W1 + lw + (size_t)row * H_);
                w1f[nt][ks][0] = wr[kw];
                w1f[nt][ks][1] = wr[kw + 4];
            }
#pragma unroll
        for (int ks = 0; ks < 8; ks++) {
            int row = cg0 + g;
            int kw = warp * 64 + ks * 8 + tg;
            const uint32_t* wr = (const uint32_t*)(g_wghh16 + lw + (size_t)row * H_);
            w2h[ks][0] = wr[kw];
            w2h[ks][1] = wr[kw + 4];
            const uint32_t* wr2 = (const uint32_t*)(g_wghl16 + lw + (size_t)row * H_);
            w2l[ks][0] = wr2[kw];
            w2l[ks][1] = wr2[kw + 4];
        }
    }

    // epilogue index maps
    const int e1b0 = tid >> 4,          e1c0 = tid & 15;           // o = tid
    const int e1b1 = (tid + 256) >> 4,  e1c1 = (tid + 256) & 15;   // o = tid+256
    const int e2b = tid >> 3, e2c = tid & 7;
    const int j2 = cg0 + e2c;

    // prefetch phase-1 gx for t=0
    float gxp0 = __ldcg(&g_gx[((size_t)0 * B_ + e1b0) * N3_ + goff + c1 + e1c0]);
    float gxp1 = __ldcg(&g_gx[((size_t)0 * B_ + e1b1) * N3_ + goff + c1 + e1c1]);

    for (int t = 0; t < S_; t++) {
        // ================= phase 1: z and r =================
        // own-col fp32 h for r*h (written by other blocks last step -> ldcg)
        float hown0 = 0.f, hown1 = 0.f;
        if (gate) {
            hown0 = __ldcg(&g_h[e1b0 * H_ + c1 + e1c0]);
            hown1 = __ldcg(&g_h[e1b1 * H_ + c1 + e1c1]);
        }
        stage_one(g_hf, s_t0);
        // prefetch phase-2 constants (safe: constant buffer / own-written h)
        float gxg = __ldcg(&g_gx[((size_t)t * B_ + e2b) * N3_ + 2 * H_ + j2]);
        float hv = g_h[e2b * H_ + j2];       // own cols, written by this block
        __syncthreads();

        float acc[2][2][4];
#pragma unroll
        for (int mt = 0; mt < 2; mt++)
#pragma unroll
            for (int nt = 0; nt < 2; nt++)
#pragma unroll
                for (int i = 0; i < 4; i++) acc[mt][nt][i] = 0.f;

#pragma unroll
        for (int ks = 0; ks < 8; ks++) {
            const int kw = warp * 64 + ks * 8 + tg;
            uint32_t ah[2][4];
#pragma unroll
            for (int mt = 0; mt < 2; mt++) {
                const uint32_t* b0 = s_t0 + (mt * 16 + g) * SW_PW;
                const uint32_t* b1 = b0 + 8 * SW_PW;
                ah[mt][0] = b0[kw];
                ah[mt][1] = b1[kw];
                ah[mt][2] = b0[kw + 4];
                ah[mt][3] = b1[kw + 4];
            }
#pragma unroll
            for (int mt = 0; mt < 2; mt++)
#pragma unroll
                for (int nt = 0; nt < 2; nt++)
                    mma_f16(acc[mt][nt], ah[mt], w1f[nt][ks]);
        }

        // cross-warp K reduction
#pragma unroll
        for (int mt = 0; mt < 2; mt++)
#pragma unroll
            for (int nt = 0; nt < 2; nt++)
#pragma unroll
                for (int i = 0; i < 4; i++) {
                    int row = mt * 16 + g + (i >> 1) * 8;
                    int col = nt * 8 + tg * 2 + (i & 1);
                    red[(warp * 32 + row) * RED_STRIDE + col] = acc[mt][nt][i];
                }
        __syncthreads();

        {
            float v0 = 0.f, v1 = 0.f;
#pragma unroll
            for (int w = 0; w < 8; w++) {
                v0 += red[(w * 32 + e1b0) * RED_STRIDE + e1c0];
                v1 += red[(w * 32 + e1b1) * RED_STRIDE + e1c1];
            }
            float s0 = sigmoidf_(v0 + gxp0);
            float s1 = sigmoidf_(v1 + gxp1);
            if (gate == 0) {
                g_z[e1b0 * H_ + c1 + e1c0] = s0;
                g_z[e1b1 * H_ + c1 + e1c1] = s1;
            } else {
                float rh0 = s0 * hown0;
                float rh1 = s1 * hown1;
                unsigned short hh, hl;
                split16(rh0, hh, hl);
                g_rhh[e1b0 * H_ + c1 + e1c0] = hh;
                g_rhl[e1b0 * H_ + c1 + e1c0] = hl;
                split16(rh1, hh, hl);
                g_rhh[e1b1 * H_ + c1 + e1c1] = hh;
                g_rhl[e1b1 * H_ + c1 + e1c1] = hl;
            }
        }

        grid_sync();

        // ================= phase 2: g and h update =================
        float zv = __ldcg(&g_z[e2b * H_ + j2]);   // safe post-barrier
        stage_two(g_rhh, g_rhl, s_t0, s_t1);
        __syncthreads();

        float acc2[2][4];
#pragma unroll
        for (int mt = 0; mt < 2; mt++)
#pragma unroll
            for (int i = 0; i < 4; i++) acc2[mt][i] = 0.f;

#pragma unroll
        for (int ks = 0; ks < 8; ks++) {
            const int kw = warp * 64 + ks * 8 + tg;
            uint32_t ah[2][4], al[2][4];
#pragma unroll
            for (int mt = 0; mt < 2; mt++) {
                const uint32_t* b0 = s_t0 + (mt * 16 + g) * SW_PW;
                const uint32_t* b1 = b0 + 8 * SW_PW;
                ah[mt][0] = b0[kw];
                ah[mt][1] = b1[kw];
                ah[mt][2] = b0[kw + 4];
                ah[mt][3] = b1[kw + 4];
                const uint32_t* c0 = s_t1 + (mt * 16 + g) * SW_PW;
                const uint32_t* c1p = c0 + 8 * SW_PW;
                al[mt][0] = c0[kw];
                al[mt][1] = c1p[kw];
                al[mt][2] = c0[kw + 4];
                al[mt][3] = c1p[kw + 4];
            }
#pragma unroll
            for (int mt = 0; mt < 2; mt++) {
                mma_f16(acc2[mt], ah[mt], w2h[ks]);
                mma_f16(acc2[mt], ah[mt], w2l[ks]);
                mma_f16(acc2[mt], al[mt], w2h[ks]);
            }
        }

#pragma unroll
        for (int mt = 0; mt < 2; mt++)
#pragma unroll
            for (int i = 0; i < 4; i++) {
                int row = mt * 16 + g + (i >> 1) * 8;
                int col = tg * 2 + (i & 1);
                red[(warp * 32 + row) * RED_STRIDE + col] = acc2[mt][i];
            }
        __syncthreads();

        {
            float v = 0.f;
#pragma unroll
            for (int w = 0; w < 8; w++) v += red[(w * 32 + e2b) * RED_STRIDE + e2c];
            size_t row = (size_t)t * B_ + e2b;
            float gv = tanhf(v + gxg);
            float hn = fmaf(zv, gv - hv, hv);

            g_h[e2b * H_ + j2] = hn;
            g_hf[e2b * H_ + j2] = __half_as_ushort(__float2half(hn));
            unsigned short bh, bl;
            split1(hn, bh, bl);
            g_seqh[row * H_ + j2] = bh;
            g_seql[row * H_ + j2] = bl;
            if (hid_out && t == S_ - 1)
                hid_out[((size_t)e2b * L_ + layer) * H_ + j2] = hn;
        }

        // prefetch next step's phase-1 gx (constant data)
        if (t + 1 < S_) {
            gxp0 = __ldcg(&g_gx[((size_t)(t + 1) * B_ + e1b0) * N3_ + goff + c1 + e1c0]);
            gxp1 = __ldcg(&g_gx[((size_t)(t + 1) * B_ + e1b1) * N3_ + goff + c1 + e1c1]);
        }

        grid_sync();
    }
}

// ---------------------------------------------------------------------------
// Launch
// ---------------------------------------------------------------------------
extern "C" void kernel_launch(void* const* d_in, const int* in_sizes, int n_in,
                              void* d_out, int out_size) {
    (void)in_sizes; (void)n_in;
    const float* x   = (const float*)d_in[0];
    const float* h0  = (const float*)d_in[1];
    const float* Wzx = (const float*)d_in[2];
    const float* bz  = (const float*)d_in[3];
    const float* Wzh = (const float*)d_in[4];
    const float* Wrx = (const float*)d_in[5];
    const float* br  = (const float*)d_in[6];
    const float* Wrh = (const float*)d_in[7];
    const float* Wgx = (const float*)d_in[8];
    const float* bg  = (const float*)d_in[9];
    const float* Wgh = (const float*)d_in[10];
    const float* Wo  = (const float*)d_in[11];
    const float* bo  = (const float*)d_in[12];

    float* out = (float*)d_out;
    float* y_out = out;
    const long long need = (long long)B_ * S_ * OUT_ + (long long)B_ * L_ * H_;
    float* hid_out = ((long long)out_size >= need) ? out + (size_t)B_ * S_ * OUT_
                                                   : nullptr;

    cudaFuncSetAttribute(k_gru_recur,
        cudaFuncAttributeMaxDynamicSharedMemorySize, SMEMR);

    // operand prep
    k_transpose_x<<<M_, 256>>>(x);
    const int wbig4 = (L_ * H_ * IN_) / 4;   // 524288
    const int wout4 = (OUT_ * H_) / 4;       // 262144
    k_split<<<wbig4 / 256, 256>>>(Wzx, 0, wbig4);
    k_split<<<wbig4 / 256, 256>>>(Wrx, 1, wbig4);
    k_split<<<wbig4 / 256, 256>>>(Wgx, 2, wbig4);
    k_split<<<wout4 / 256, 256>>>(Wo, 3, wout4);
    k_split16<<<wbig4 / 256, 256>>>(Wzh, 0, wbig4);
    k_split16<<<wbig4 / 256, 256>>>(Wrh, 1, wbig4);
    k_split16<<<wbig4 / 256, 256>>>(Wgh, 2, wbig4);

    dim3 tgrid(1024 / 64, M_ / 128);   // (16, 128)

    for (int layer = 0; layer < L_; layer++) {
        k_prep<<<(B_ * H_) / 256, 256>>>(h0, layer);

        const int woff = layer * H_ * IN_;
        k_hmma<<<tgrid, 256>>>(layer, 0, woff, bz + (size_t)layer * H_,
                               nullptr, N3_, 0, 0);
        k_hmma<<<tgrid, 256>>>(layer, 1, woff, br + (size_t)layer * H_,
                               nullptr, N3_, H_, 0);
        k_hmma<<<tgrid, 256>>>(layer, 2, woff, bg + (size_t)layer * H_,
                               nullptr, N3_, 2 * H_, 0);

        k_gru_recur<<<NBLK, 256, SMEMR>>>(layer, hid_out);
    }

    // output projection
    k_hmma<<<tgrid, 256>>>(1, 3, 0, bo, y_out, OUT_, 0, 1);
}